// round 12
// baseline (speedup 1.0000x reference)
#include <cuda_runtime.h>
#include <cuda_fp16.h>
#include <cstdint>

// ===========================================================================
// B=16384, Q=1024, F=2. mma.sync m16n8k16 fp16 single-plane (1 MMA term).
// Main GEMM: CTA 256x128, warp 64x64, 4-stage cp.async ring.
// GEMM2+GEMM3+qs fused into one dual-accumulator kernel (128x128 tile).
// GEMM4+GEMM5 fused algebraically: out = qs @ (Wout*Wv)^T + (Wout*bv+bout).
// ===========================================================================

#define DEVI __device__ __forceinline__

DEVI uint32_t smem_u32(const void* p) {
    uint32_t r;
    asm("{ .reg .u64 t; cvta.to.shared.u64 t, %1; cvt.u32.u64 %0, t; }"
        : "=r"(r) : "l"(p));
    return r;
}
DEVI uint32_t swz(uint32_t x) { return x ^ ((x >> 3) & 0x70); }

DEVI void cp16(uint32_t dst, const void* src) {
    asm volatile("cp.async.cg.shared.global [%0], [%1], 16;"
                 :: "r"(dst), "l"(src));
}
#define CP_COMMIT() asm volatile("cp.async.commit_group;" ::: "memory")
#define CP_WAIT(n)  asm volatile("cp.async.wait_group %0;" :: "n"(n) : "memory")

DEVI void ldsm4(uint32_t* r, uint32_t a) {
    asm volatile("ldmatrix.sync.aligned.m8n8.x4.shared.b16 {%0,%1,%2,%3}, [%4];"
                 : "=r"(r[0]), "=r"(r[1]), "=r"(r[2]), "=r"(r[3]) : "r"(a));
}
DEVI void mma_f16(float* d, const uint32_t* a, const uint32_t* b) {
    asm volatile("mma.sync.aligned.m16n8k16.row.col.f32.f16.f16.f32 "
                 "{%0,%1,%2,%3},{%4,%5,%6,%7},{%8,%9},{%0,%1,%2,%3};"
                 : "+f"(d[0]), "+f"(d[1]), "+f"(d[2]), "+f"(d[3])
                 : "r"(a[0]), "r"(a[1]), "r"(a[2]), "r"(a[3]),
                   "r"(b[0]), "r"(b[1]));
}

DEVI void split_h(float v, __half& h, __half& l) {
    h = __float2half_rn(v);
    l = __float2half_rn(v - __half2float(h));
}
DEVI uint32_t pack2h(float a, float b) {
    __half2 p = __floats2half2_rn(a, b);
    return *(uint32_t*)&p;
}

// ---------------------------------------------------------------------------
// Scratch
// ---------------------------------------------------------------------------
__device__ __half g_h1  [(size_t)16384 * 4096];
__device__ __half g_pq  [(size_t)16384 * 2048];
__device__ __half g_t2p [(size_t)16384 * 2048];   // pre-LN t2 (fp16)
__device__ __half g_t2q [(size_t)16384 * 2048];   // post-LN tanh (fp16)
__device__ __half g_qs  [(size_t)16384 * 1024];
__device__ __half g_w2  [(size_t)2048 * 4096];
__device__ __half g_w3  [(size_t)1024 * 2048];
__device__ __half g_pw2 [(size_t)1024 * 2048];
__device__ __half g_wvth[(size_t)1024 * 1024], g_wvtl[(size_t)1024 * 1024];
__device__ __half g_woh [(size_t)1024 * 1024], g_wol [(size_t)1024 * 1024];
__device__ float  g_wff [(size_t)1024 * 1024];
__device__ __half g_wf  [(size_t)1024 * 1024];
__device__ float  g_bfused[1024];
__device__ float  g_bzero[1024];

// ---------------------------------------------------------------------------
// Main GEMM (1-term): C[m,n] = sum_k A[m,k]*W[n,k] + bias[n]
// CTA 256x128, 8 warps 4(m)x2(n), warp tile 64x64, 4-stage ring.
// EPI: 0 = fp32 store; 2 = fp16 store
// ---------------------------------------------------------------------------
template<int EPI>
__global__ __launch_bounds__(256, 1)
void gemm_f16(const __half* __restrict__ A, const __half* __restrict__ W,
              const float* __restrict__ bias, float* __restrict__ Cf,
              __half* __restrict__ Chf, int N, int K)
{
    extern __shared__ char smem[];
    const uint32_t sb = smem_u32(smem);
    const uint32_t TILES = (sb + 1023u) & ~1023u;
    const uint32_t STG = 49152;   // A 32KB | W 16KB

    const int tid = threadIdx.x, wid = tid >> 5, lane = tid & 31;
    const int bm = blockIdx.y * 256, bn = blockIdx.x * 128;
    const int warp_m = wid & 3, warp_n = wid >> 2;
    const int nC = K >> 6;

    auto load_chunk = [&](int ci, int s) {
        const int k0 = ci << 6;
        const uint32_t stg = TILES + s * STG;
#pragma unroll
        for (int t = 0; t < 8; t++) {
            const int g = tid + t * 256;
            const int row = g >> 3;
            const int col8 = (g & 7) * 8;
            const uint32_t so = swz((uint32_t)(row * 128 + col8 * 2));
            cp16(stg + so, A + (size_t)(bm + row) * K + k0 + col8);
        }
#pragma unroll
        for (int t = 0; t < 4; t++) {
            const int g = tid + t * 256;
            const int row = g >> 3;
            const int col8 = (g & 7) * 8;
            const uint32_t so = swz((uint32_t)(row * 128 + col8 * 2));
            cp16(stg + 32768 + so, W + (size_t)(bn + row) * K + k0 + col8);
        }
        CP_COMMIT();
    };

    const uint32_t mA = warp_m * 64 + ((lane >> 3) & 1) * 8 + (lane & 7);
    const uint32_t kA = (lane >> 4) * 8;
    const uint32_t nB = warp_n * 64 + (lane >> 4) * 8 + (lane & 7);
    const uint32_t kB = ((lane >> 3) & 1) * 8;

    float acc[4][8][4];
#pragma unroll
    for (int i = 0; i < 4; i++)
#pragma unroll
        for (int j = 0; j < 8; j++)
#pragma unroll
            for (int e = 0; e < 4; e++) acc[i][j][e] = 0.f;

    load_chunk(0, 0);
    if (nC > 1) load_chunk(1, 1);
    if (nC > 2) load_chunk(2, 2);

    for (int i = 0; i < nC; i++) {
        const int s = i & 3;
        if (i < nC - 2)       { CP_WAIT(2); }
        else if (i == nC - 2) { CP_WAIT(1); }
        else                  { CP_WAIT(0); }
        __syncthreads();
        if (i + 3 < nC) load_chunk(i + 3, (i + 3) & 3);

        const uint32_t stg = TILES + s * STG;
        const uint32_t Ab = stg, Bb = stg + 32768;

#pragma unroll
        for (int ks = 0; ks < 4; ks++) {
            uint32_t bh[4][4];
#pragma unroll
            for (int g = 0; g < 4; g++) {
                const uint32_t oB = swz((nB + g * 16) * 128 + (ks * 16 + kB) * 2);
                ldsm4(bh[g], Bb + oB);
            }
#pragma unroll
            for (int mi = 0; mi < 4; mi++) {
                const uint32_t oA = swz((mA + mi * 16) * 128 + (ks * 16 + kA) * 2);
                uint32_t ah[4];
                ldsm4(ah, Ab + oA);
#pragma unroll
                for (int ni = 0; ni < 8; ni++)
                    mma_f16(acc[mi][ni], ah, &bh[ni >> 1][(ni & 1) * 2]);
            }
        }
    }

    const int r0l   = lane >> 2;
    const int cpair = (lane & 3) * 2;
    const int mbase = bm + warp_m * 64;
    const int nbase = bn + warp_n * 64;

#pragma unroll
    for (int mi = 0; mi < 4; mi++) {
        const int row0 = mbase + mi * 16 + r0l;
        const int row1 = row0 + 8;
#pragma unroll
        for (int ni = 0; ni < 8; ni++) {
            const int col = nbase + ni * 8 + cpair;
            const float2 bv = *(const float2*)&bias[col];
            const float v0 = acc[mi][ni][0] + bv.x;
            const float v1 = acc[mi][ni][1] + bv.y;
            const float v2 = acc[mi][ni][2] + bv.x;
            const float v3 = acc[mi][ni][3] + bv.y;
            if (EPI == 2) {
                *(uint32_t*)&Chf[(size_t)row0 * N + col] = pack2h(v0, v1);
                *(uint32_t*)&Chf[(size_t)row1 * N + col] = pack2h(v2, v3);
            } else {
                *(float2*)&Cf[(size_t)row0 * N + col] = make_float2(v0, v1);
                *(float2*)&Cf[(size_t)row1 * N + col] = make_float2(v2, v3);
            }
        }
    }
}

// ---------------------------------------------------------------------------
// Fused dual GEMM + qs epilogue. CTA 128x128, warp 64x32, acc1+acc2.
//   amp   = t2q @ W3^T  + b3
//   phase = tanh(pq @ pW2^T + pb2)
//   qs    = (sin(amp*f0+p0) + cos(phase*f1+p1) + tanh(p2)) / 3  -> fp16
// ---------------------------------------------------------------------------
__global__ __launch_bounds__(256, 1)
void gemm_dual_qs(const __half* __restrict__ A1, const __half* __restrict__ W1,
                  const float* __restrict__ b1,
                  const __half* __restrict__ A2, const __half* __restrict__ W2,
                  const float* __restrict__ b2,
                  const float* __restrict__ rf, const float* __restrict__ rp,
                  __half* __restrict__ qs, int K)
{
    extern __shared__ char smem[];
    const uint32_t sb = smem_u32(smem);
    const uint32_t TILES = (sb + 1023u) & ~1023u;
    const uint32_t STG = 32768;   // A 16KB | W 16KB, 4 stages

    const int tid = threadIdx.x, wid = tid >> 5, lane = tid & 31;
    const int bm = blockIdx.y * 128, bn = blockIdx.x * 128;
    const int warp_m = wid & 1, warp_n = wid >> 1;
    const int nC = K >> 6;
    const int N = 1024;

    const uint32_t mA = warp_m * 64 + ((lane >> 3) & 1) * 8 + (lane & 7);
    const uint32_t kA = (lane >> 4) * 8;
    const uint32_t nB = warp_n * 32 + (lane >> 4) * 8 + (lane & 7);
    const uint32_t kB = ((lane >> 3) & 1) * 8;

    float acc1[4][4][4], acc2[4][4][4];
#pragma unroll
    for (int i = 0; i < 4; i++)
#pragma unroll
        for (int j = 0; j < 4; j++)
#pragma unroll
            for (int e = 0; e < 4; e++) { acc1[i][j][e] = 0.f; acc2[i][j][e] = 0.f; }

    auto run_gemm = [&](const __half* A, const __half* W, float (*acc)[4][4]) {
        auto load_chunk = [&](int ci, int s) {
            const int k0 = ci << 6;
            const uint32_t stg = TILES + s * STG;
#pragma unroll
            for (int t = 0; t < 4; t++) {
                const int g = tid + t * 256;
                const int row = g >> 3;
                const int col8 = (g & 7) * 8;
                const uint32_t so = swz((uint32_t)(row * 128 + col8 * 2));
                cp16(stg + so,         A + (size_t)(bm + row) * K + k0 + col8);
                cp16(stg + 16384 + so, W + (size_t)(bn + row) * K + k0 + col8);
            }
            CP_COMMIT();
        };

        load_chunk(0, 0);
        if (nC > 1) load_chunk(1, 1);
        if (nC > 2) load_chunk(2, 2);

        for (int i = 0; i < nC; i++) {
            const int s = i & 3;
            if (i < nC - 2)       { CP_WAIT(2); }
            else if (i == nC - 2) { CP_WAIT(1); }
            else                  { CP_WAIT(0); }
            __syncthreads();
            if (i + 3 < nC) load_chunk(i + 3, (i + 3) & 3);

            const uint32_t stg = TILES + s * STG;
            const uint32_t Ab = stg, Bb = stg + 16384;

#pragma unroll
            for (int ks = 0; ks < 4; ks++) {
                const uint32_t oB0 = swz(nB * 128 + (ks * 16 + kB) * 2);
                const uint32_t oB1 = swz((nB + 16) * 128 + (ks * 16 + kB) * 2);
                uint32_t bh0[4], bh1[4];
                ldsm4(bh0, Bb + oB0);
                ldsm4(bh1, Bb + oB1);
#pragma unroll
                for (int mi = 0; mi < 4; mi++) {
                    const uint32_t oA = swz((mA + mi * 16) * 128 + (ks * 16 + kA) * 2);
                    uint32_t ah[4];
                    ldsm4(ah, Ab + oA);
#pragma unroll
                    for (int ni = 0; ni < 4; ni++) {
                        const uint32_t* bp = (ni < 2) ? &bh0[(ni & 1) * 2]
                                                      : &bh1[(ni & 1) * 2];
                        mma_f16(acc[mi][ni], ah, bp);
                    }
                }
            }
        }
        __syncthreads();   // drain before smem reuse by the next GEMM
    };

    run_gemm(A1, W1, acc1);
    run_gemm(A2, W2, acc2);

    // ---- qs epilogue ----
    const int r0l   = lane >> 2;
    const int cpair = (lane & 3) * 2;
    const int mbase = bm + warp_m * 64;
    const int nbase = bn + warp_n * 32;
    const float* rfb = rf + 4 * 1024 * 3;
    const float* rpb = rp + 4 * 1024 * 3;

#pragma unroll
    for (int ni = 0; ni < 4; ni++) {
        const int col = nbase + ni * 8 + cpair;
        const float2 b1v = *(const float2*)&b1[col];
        const float2 b2v = *(const float2*)&b2[col];
        const float f0a = rfb[3 * col + 0],     f1a = rfb[3 * col + 1];
        const float p0a = rpb[3 * col + 0],     p1a = rpb[3 * col + 1];
        const float rza = tanhf(rpb[3 * col + 2]);
        const float f0b = rfb[3 * (col + 1) + 0], f1b = rfb[3 * (col + 1) + 1];
        const float p0b = rpb[3 * (col + 1) + 0], p1b = rpb[3 * (col + 1) + 1];
        const float rzb = tanhf(rpb[3 * (col + 1) + 2]);
#pragma unroll
        for (int mi = 0; mi < 4; mi++) {
            const int row0 = mbase + mi * 16 + r0l;
            const int row1 = row0 + 8;
            const float a0 = acc1[mi][ni][0] + b1v.x;
            const float a1 = acc1[mi][ni][1] + b1v.y;
            const float a2 = acc1[mi][ni][2] + b1v.x;
            const float a3 = acc1[mi][ni][3] + b1v.y;
            const float h0 = tanhf(acc2[mi][ni][0] + b2v.x);
            const float h1 = tanhf(acc2[mi][ni][1] + b2v.y);
            const float h2 = tanhf(acc2[mi][ni][2] + b2v.x);
            const float h3 = tanhf(acc2[mi][ni][3] + b2v.y);
            const float q0 = (sinf(fmaf(a0, f0a, p0a)) + cosf(fmaf(h0, f1a, p1a)) + rza) * (1.f / 3.f);
            const float q1 = (sinf(fmaf(a1, f0b, p0b)) + cosf(fmaf(h1, f1b, p1b)) + rzb) * (1.f / 3.f);
            const float q2 = (sinf(fmaf(a2, f0a, p0a)) + cosf(fmaf(h2, f1a, p1a)) + rza) * (1.f / 3.f);
            const float q3 = (sinf(fmaf(a3, f0b, p0b)) + cosf(fmaf(h3, f1b, p1b)) + rzb) * (1.f / 3.f);
            *(uint32_t*)&qs[(size_t)row0 * N + col] = pack2h(q0, q1);
            *(uint32_t*)&qs[(size_t)row1 * N + col] = pack2h(q2, q3);
        }
    }
}

// ---------------------------------------------------------------------------
// Precompute GEMM (3-term, 2-plane both operands): Wfused = Wout @ Wv^T
// ---------------------------------------------------------------------------
__global__ __launch_bounds__(256, 1)
void gemm3_pre(const __half* __restrict__ Ah, const __half* __restrict__ Al,
               const __half* __restrict__ Wh, const __half* __restrict__ Wl,
               const float* __restrict__ bias, float* __restrict__ Cf,
               int N, int K)
{
    extern __shared__ char smem[];
    const uint32_t sb = smem_u32(smem);
    const uint32_t TILES = (sb + 1023u) & ~1023u;
    const uint32_t STG = 65536;

    const int tid = threadIdx.x, wid = tid >> 5, lane = tid & 31;
    const int bm = blockIdx.y * 128, bn = blockIdx.x * 128;
    const int warp_m = wid & 1, warp_n = wid >> 1;
    const int nC = K >> 6;

    auto load_chunk = [&](int ci, int s) {
        const int k0 = ci << 6;
        const uint32_t stg = TILES + s * STG;
#pragma unroll
        for (int t = 0; t < 4; t++) {
            const int g = tid + t * 256;
            const int row = g >> 3;
            const int col8 = (g & 7) * 8;
            const uint32_t so = swz((uint32_t)(row * 128 + col8 * 2));
            const size_t ia = (size_t)(bm + row) * K + k0 + col8;
            const size_t ib = (size_t)(bn + row) * K + k0 + col8;
            cp16(stg + so,         Ah + ia);
            cp16(stg + 16384 + so, Al + ia);
            cp16(stg + 32768 + so, Wh + ib);
            cp16(stg + 49152 + so, Wl + ib);
        }
        CP_COMMIT();
    };

    const uint32_t mA = warp_m * 64 + ((lane >> 3) & 1) * 8 + (lane & 7);
    const uint32_t kA = (lane >> 4) * 8;
    const uint32_t nB = warp_n * 32 + (lane >> 4) * 8 + (lane & 7);
    const uint32_t kB = ((lane >> 3) & 1) * 8;

    float acc[4][4][4];
#pragma unroll
    for (int i = 0; i < 4; i++)
#pragma unroll
        for (int j = 0; j < 4; j++)
#pragma unroll
            for (int e = 0; e < 4; e++) acc[i][j][e] = 0.f;

    load_chunk(0, 0);
    if (nC > 1) load_chunk(1, 1);

    for (int i = 0; i < nC; i++) {
        const int s = i - (i / 3) * 3;
        if (i < nC - 1) { CP_WAIT(1); } else { CP_WAIT(0); }
        __syncthreads();
        if (i + 2 < nC) load_chunk(i + 2, (i + 2) - ((i + 2) / 3) * 3);

        const uint32_t stg = TILES + s * STG;
        const uint32_t Ahb = stg, Alb = stg + 16384;
        const uint32_t Bhb = stg + 32768, Blb = stg + 49152;

#pragma unroll
        for (int ks = 0; ks < 4; ks++) {
            const uint32_t oB0 = swz(nB * 128 + (ks * 16 + kB) * 2);
            const uint32_t oB1 = swz((nB + 16) * 128 + (ks * 16 + kB) * 2);
            uint32_t bh0[4], bh1[4], bl0[4], bl1[4];
            ldsm4(bh0, Bhb + oB0);
            ldsm4(bh1, Bhb + oB1);
            ldsm4(bl0, Blb + oB0);
            ldsm4(bl1, Blb + oB1);
#pragma unroll
            for (int mi = 0; mi < 4; mi++) {
                const uint32_t oA = swz((mA + mi * 16) * 128 + (ks * 16 + kA) * 2);
                uint32_t ah[4], al[4];
                ldsm4(ah, Ahb + oA);
                ldsm4(al, Alb + oA);
#pragma unroll
                for (int ni = 0; ni < 4; ni++) {
                    const uint32_t* bhp = (ni < 2) ? &bh0[(ni & 1) * 2] : &bh1[(ni & 1) * 2];
                    const uint32_t* blp = (ni < 2) ? &bl0[(ni & 1) * 2] : &bl1[(ni & 1) * 2];
                    mma_f16(acc[mi][ni], ah, bhp);
                    mma_f16(acc[mi][ni], ah, blp);
                    mma_f16(acc[mi][ni], al, bhp);
                }
            }
        }
        __syncthreads();
    }

    const int r0l   = lane >> 2;
    const int cpair = (lane & 3) * 2;
    const int mbase = bm + warp_m * 64;
    const int nbase = bn + warp_n * 32;
#pragma unroll
    for (int mi = 0; mi < 4; mi++) {
        const int row0 = mbase + mi * 16 + r0l;
        const int row1 = row0 + 8;
#pragma unroll
        for (int ni = 0; ni < 4; ni++) {
            const int col = nbase + ni * 8 + cpair;
            const float2 bv = *(const float2*)&bias[col];
            *(float2*)&Cf[(size_t)row0 * N + col] =
                make_float2(acc[mi][ni][0] + bv.x, acc[mi][ni][1] + bv.y);
            *(float2*)&Cf[(size_t)row1 * N + col] =
                make_float2(acc[mi][ni][2] + bv.x, acc[mi][ni][3] + bv.y);
        }
    }
}

// ---------------------------------------------------------------------------
DEVI float2 block_reduce2(float2 v, float2* sbuf) {
    const int lane = threadIdx.x & 31, wid = threadIdx.x >> 5;
#pragma unroll
    for (int o = 16; o > 0; o >>= 1) {
        v.x += __shfl_xor_sync(0xffffffffu, v.x, o);
        v.y += __shfl_xor_sync(0xffffffffu, v.y, o);
    }
    if (lane == 0) sbuf[wid] = v;
    __syncthreads();
    if (wid == 0) {
        float2 t = (lane < 8) ? sbuf[lane] : make_float2(0.f, 0.f);
#pragma unroll
        for (int o = 4; o > 0; o >>= 1) {
            t.x += __shfl_xor_sync(0xffffffffu, t.x, o);
            t.y += __shfl_xor_sync(0xffffffffu, t.y, o);
        }
        if (lane == 0) sbuf[0] = t;
    }
    __syncthreads();
    float2 r = sbuf[0];
    __syncthreads();
    return r;
}

// ---------------------------------------------------------------------------
// Layer-1: 8 rows/block, weights cached in smem; fp16 outputs
// ---------------------------------------------------------------------------
__global__ __launch_bounds__(256)
void layer1_k(const float* __restrict__ x,
              const float* __restrict__ aW1, const float* __restrict__ ab1,
              const float* __restrict__ ag1, const float* __restrict__ abe1,
              const float* __restrict__ pW1, const float* __restrict__ pb1,
              const float* __restrict__ pg1, const float* __restrict__ pbe1,
              __half* __restrict__ h1, __half* __restrict__ pq)
{
    extern __shared__ float sw[];
    float2* W  = (float2*)sw;
    float*  Bb = sw + 8192;
    float*  Gg = sw + 12288;
    float*  Be = sw + 16384;
    __shared__ float2 sbuf[8];

    const int tid = threadIdx.x;
    const int rb = blockIdx.x * 8;

    for (int i = tid; i < 4096; i += 256) {
        W[i]  = ((const float2*)aW1)[i];
        Bb[i] = ab1[i]; Gg[i] = ag1[i]; Be[i] = abe1[i];
    }
    __syncthreads();
    for (int r = 0; r < 8; r++) {
        const int b = rb + r;
        const float x0 = x[2 * b], x1 = x[2 * b + 1];
        float2 ss = make_float2(0.f, 0.f);
#pragma unroll
        for (int t = 0; t < 16; t++) {
            const int i = tid + t * 256;
            const float v = fmaf(W[i].y, x1, fmaf(W[i].x, x0, Bb[i]));
            ss.x += v; ss.y += v * v;
        }
        const float2 rr = block_reduce2(ss, sbuf);
        const float m = rr.x * (1.f / 4096.f);
        const float rstd = rsqrtf(rr.y * (1.f / 4096.f) - m * m + 1e-5f);
#pragma unroll
        for (int t = 0; t < 16; t++) {
            const int i = tid + t * 256;
            const float v = fmaf(W[i].y, x1, fmaf(W[i].x, x0, Bb[i]));
            const float hh = (v - m) * rstd * Gg[i] + Be[i];
            const float g = 0.5f * hh * (1.f + erff(hh * 0.70710678118654752f));
            h1[(size_t)b * 4096 + i] = __float2half_rn(g);
        }
    }
    __syncthreads();

    for (int i = tid; i < 2048; i += 256) {
        W[i]  = ((const float2*)pW1)[i];
        Bb[i] = pb1[i]; Gg[i] = pg1[i]; Be[i] = pbe1[i];
    }
    __syncthreads();
    for (int r = 0; r < 8; r++) {
        const int b = rb + r;
        const float x0 = x[2 * b], x1 = x[2 * b + 1];
        float2 ss = make_float2(0.f, 0.f);
#pragma unroll
        for (int t = 0; t < 8; t++) {
            const int i = tid + t * 256;
            const float v = fmaf(W[i].y, x1, fmaf(W[i].x, x0, Bb[i]));
            ss.x += v; ss.y += v * v;
        }
        const float2 rr = block_reduce2(ss, sbuf);
        const float m = rr.x * (1.f / 2048.f);
        const float rstd = rsqrtf(rr.y * (1.f / 2048.f) - m * m + 1e-5f);
#pragma unroll
        for (int t = 0; t < 8; t++) {
            const int i = tid + t * 256;
            const float v = fmaf(W[i].y, x1, fmaf(W[i].x, x0, Bb[i]));
            const float hh = (v - m) * rstd * Gg[i] + Be[i];
            pq[(size_t)b * 2048 + i] = __float2half_rn(hh / (1.f + expf(-hh)));
        }
    }
}

// ---------------------------------------------------------------------------
// LN + tanh over row of 2048, fp16 in -> fp16 out
// ---------------------------------------------------------------------------
__global__ __launch_bounds__(256)
void ln_tanh_kernel(const __half* __restrict__ in,
                    const float* __restrict__ g, const float* __restrict__ be,
                    __half* __restrict__ oq)
{
    __shared__ float2 sbuf[8];
    const int b = blockIdx.x, tid = threadIdx.x;
    const __half* row = in + (size_t)b * 2048;
    float va[8];
    float2 ss = make_float2(0.f, 0.f);
#pragma unroll
    for (int t = 0; t < 8; t++) {
        const int i = tid + t * 256;
        const float v = __half2float(row[i]);
        va[t] = v; ss.x += v; ss.y += v * v;
    }
    const float2 r = block_reduce2(ss, sbuf);
    const float m = r.x * (1.f / 2048.f);
    const float rstd = rsqrtf(r.y * (1.f / 2048.f) - m * m + 1e-5f);
#pragma unroll
    for (int t = 0; t < 8; t++) {
        const int i = tid + t * 256;
        oq[(size_t)b * 2048 + i] =
            __float2half_rn(tanhf((va[t] - m) * rstd * g[i] + be[i]));
    }
}

// ---------------------------------------------------------------------------
__global__ __launch_bounds__(256)
void wconv_kernel(const float* __restrict__ s, __half* __restrict__ h, int n)
{
    const int i = blockIdx.x * 256 + threadIdx.x;
    if (i < n) h[i] = __float2half_rn(s[i]);
}

__global__ __launch_bounds__(256)
void wsplit_kernel(const float* __restrict__ s,
                   __half* __restrict__ h, __half* __restrict__ l, int n)
{
    const int i = blockIdx.x * 256 + threadIdx.x;
    if (i < n) {
        __half hh, ll;
        split_h(s[i], hh, ll);
        h[i] = hh; l[i] = ll;
    }
}

__global__ void tsplit_kernel(const float* __restrict__ W,
                              __half* __restrict__ th, __half* __restrict__ tl)
{
    __shared__ float tile[32][33];
    const int tx = threadIdx.x, ty = threadIdx.y;
    const int bx = blockIdx.x * 32, by = blockIdx.y * 32;
#pragma unroll
    for (int r = 0; r < 4; r++)
        tile[ty * 4 + r][tx] = W[(size_t)(by + ty * 4 + r) * 1024 + bx + tx];
    __syncthreads();
#pragma unroll
    for (int r = 0; r < 4; r++) {
        const float v = tile[tx][ty * 4 + r];
        __half h, l; split_h(v, h, l);
        const size_t o = (size_t)(bx + ty * 4 + r) * 1024 + by + tx;
        th[o] = h; tl[o] = l;
    }
}

__global__ __launch_bounds__(256)
void bfuse_kernel(const float* __restrict__ Wout, const float* __restrict__ bv,
                  const float* __restrict__ bout, float* __restrict__ bf)
{
    __shared__ float2 sbuf[8];
    const int o = blockIdx.x, tid = threadIdx.x;
    float s = 0.f;
#pragma unroll
    for (int t = 0; t < 4; t++) {
        const int i = tid + t * 256;
        s = fmaf(Wout[(size_t)o * 1024 + i], bv[i], s);
    }
    const float2 r = block_reduce2(make_float2(s, 0.f), sbuf);
    if (tid == 0) bf[o] = r.x + bout[o];
}

// ---------------------------------------------------------------------------
extern "C" void kernel_launch(void* const* d_in, const int* in_sizes, int n_in,
                              void* d_out, int out_size)
{
    const float* x    = (const float*)d_in[0];
    const float* aW1  = (const float*)d_in[1];
    const float* ab1  = (const float*)d_in[2];
    const float* ag1  = (const float*)d_in[3];
    const float* abe1 = (const float*)d_in[4];
    const float* aW2  = (const float*)d_in[5];
    const float* ab2  = (const float*)d_in[6];
    const float* ag2  = (const float*)d_in[7];
    const float* abe2 = (const float*)d_in[8];
    const float* aW3  = (const float*)d_in[9];
    const float* ab3  = (const float*)d_in[10];
    const float* pW1  = (const float*)d_in[11];
    const float* pb1  = (const float*)d_in[12];
    const float* pg1  = (const float*)d_in[13];
    const float* pbe1 = (const float*)d_in[14];
    const float* pW2  = (const float*)d_in[15];
    const float* pb2  = (const float*)d_in[16];
    const float* rf   = (const float*)d_in[17];
    const float* rp   = (const float*)d_in[18];
    const float* winV = (const float*)d_in[19] + (size_t)2048 * 1024;
    const float* binV = (const float*)d_in[20] + 2048;
    const float* wout = (const float*)d_in[21];
    const float* bout = (const float*)d_in[22];
    float* out = (float*)d_out;

    __half *h1, *pq, *t2p, *t2q, *qs;
    __half *w2, *w3, *pw2, *wvth, *wvtl, *woh, *wol, *wf;
    float *wff, *bfused, *bzero;
    cudaGetSymbolAddress((void**)&h1, g_h1);
    cudaGetSymbolAddress((void**)&pq, g_pq);
    cudaGetSymbolAddress((void**)&t2p, g_t2p);
    cudaGetSymbolAddress((void**)&t2q, g_t2q);
    cudaGetSymbolAddress((void**)&qs, g_qs);
    cudaGetSymbolAddress((void**)&w2, g_w2);
    cudaGetSymbolAddress((void**)&w3, g_w3);
    cudaGetSymbolAddress((void**)&pw2, g_pw2);
    cudaGetSymbolAddress((void**)&wvth, g_wvth); cudaGetSymbolAddress((void**)&wvtl, g_wvtl);
    cudaGetSymbolAddress((void**)&woh, g_woh); cudaGetSymbolAddress((void**)&wol, g_wol);
    cudaGetSymbolAddress((void**)&wff, g_wff);
    cudaGetSymbolAddress((void**)&wf, g_wf);
    cudaGetSymbolAddress((void**)&bfused, g_bfused);
    cudaGetSymbolAddress((void**)&bzero, g_bzero);

    const int SMEMB = 1024 + 4 * 49152;
    cudaFuncSetAttribute(gemm_f16<0>, cudaFuncAttributeMaxDynamicSharedMemorySize, SMEMB);
    cudaFuncSetAttribute(gemm_f16<2>, cudaFuncAttributeMaxDynamicSharedMemorySize, SMEMB);
    const int SMEMD = 1024 + 4 * 32768;
    cudaFuncSetAttribute(gemm_dual_qs, cudaFuncAttributeMaxDynamicSharedMemorySize, SMEMD);
    const int SMEMP = 1024 + 3 * 65536;
    cudaFuncSetAttribute(gemm3_pre, cudaFuncAttributeMaxDynamicSharedMemorySize, SMEMP);
    const int L1SMEM = 81920;
    cudaFuncSetAttribute(layer1_k, cudaFuncAttributeMaxDynamicSharedMemorySize, L1SMEM);

    const int M = 16384;

    // W2 conversion first, then layer1
    wconv_kernel<<<(2048 * 4096) / 256, 256>>>(aW2, w2, 2048 * 4096);
    layer1_k<<<M / 8, 256, L1SMEM>>>(x, aW1, ab1, ag1, abe1, pW1, pb1, pg1, pbe1,
                                     h1, pq);
    wconv_kernel<<<(1024 * 2048) / 256, 256>>>(aW3, w3, 1024 * 2048);

    // GEMM1: t2pre = h1 @ W2^T + b2  (fp16 out)
    gemm_f16<2><<<dim3(16, 64), 256, SMEMB>>>(h1, w2, ab2, nullptr, t2p,
                                              2048, 4096);

    // Fused-weight precompute
    wconv_kernel<<<(1024 * 2048) / 256, 256>>>(pW2, pw2, 1024 * 2048);
    tsplit_kernel<<<dim3(32, 32), dim3(32, 8)>>>(winV, wvth, wvtl);
    wsplit_kernel<<<(1024 * 1024) / 256, 256>>>(wout, woh, wol, 1024 * 1024);
    gemm3_pre<<<dim3(8, 8), 256, SMEMP>>>(woh, wol, wvth, wvtl, bzero, wff,
                                          1024, 1024);
    bfuse_kernel<<<1024, 256>>>(wout, binV, bout, bfused);
    wconv_kernel<<<(1024 * 1024) / 256, 256>>>(wff, wf, 1024 * 1024);

    ln_tanh_kernel<<<M, 256>>>(t2p, ag2, abe2, t2q);

    // Fused GEMM2 + GEMM3 + qs epilogue -> qs fp16
    gemm_dual_qs<<<dim3(8, 128), 256, SMEMD>>>(t2q, w3, ab3,
                                               pq, pw2, pb2,
                                               rf, rp, qs, 2048);

    // out = qs @ Wfused^T + bfused
    gemm_f16<0><<<dim3(8, 64), 256, SMEMB>>>(qs, wf, bfused, out, nullptr,
                                             1024, 1024);
}

// round 13
// speedup vs baseline: 1.1475x; 1.1475x over previous
#include <cuda_runtime.h>
#include <cuda_fp16.h>
#include <cstdint>

// ===========================================================================
// B=16384, Q=1024, F=2. mma.sync m16n8k16 fp16 single-plane (1 MMA term).
// Main GEMM: CTA 256x128, warp 64x64, K-chunk 64, 4-stage cp.async ring.
// GEMM2+GEMM3 merged via gridDim.z (same kernel, fp16 out, z=1 adds tanh).
// GEMM4+GEMM5 fused algebraically: out = qs @ (Wout*Wv)^T + (Wout*bv+bout).
// All intermediates fp16 (error budget ~3.8e-4, threshold 1e-3).
// ===========================================================================

#define DEVI __device__ __forceinline__

DEVI uint32_t smem_u32(const void* p) {
    uint32_t r;
    asm("{ .reg .u64 t; cvta.to.shared.u64 t, %1; cvt.u32.u64 %0, t; }"
        : "=r"(r) : "l"(p));
    return r;
}
DEVI uint32_t swz(uint32_t x) { return x ^ ((x >> 3) & 0x70); }

DEVI void cp16(uint32_t dst, const void* src) {
    asm volatile("cp.async.cg.shared.global [%0], [%1], 16;"
                 :: "r"(dst), "l"(src));
}
#define CP_COMMIT() asm volatile("cp.async.commit_group;" ::: "memory")
#define CP_WAIT(n)  asm volatile("cp.async.wait_group %0;" :: "n"(n) : "memory")

DEVI void ldsm4(uint32_t* r, uint32_t a) {
    asm volatile("ldmatrix.sync.aligned.m8n8.x4.shared.b16 {%0,%1,%2,%3}, [%4];"
                 : "=r"(r[0]), "=r"(r[1]), "=r"(r[2]), "=r"(r[3]) : "r"(a));
}
DEVI void mma_f16(float* d, const uint32_t* a, const uint32_t* b) {
    asm volatile("mma.sync.aligned.m16n8k16.row.col.f32.f16.f16.f32 "
                 "{%0,%1,%2,%3},{%4,%5,%6,%7},{%8,%9},{%0,%1,%2,%3};"
                 : "+f"(d[0]), "+f"(d[1]), "+f"(d[2]), "+f"(d[3])
                 : "r"(a[0]), "r"(a[1]), "r"(a[2]), "r"(a[3]),
                   "r"(b[0]), "r"(b[1]));
}

DEVI void split_h(float v, __half& h, __half& l) {
    h = __float2half_rn(v);
    l = __float2half_rn(v - __half2float(h));
}
DEVI uint32_t pack2h(float a, float b) {
    __half2 p = __floats2half2_rn(a, b);
    return *(uint32_t*)&p;
}

// ---------------------------------------------------------------------------
// Scratch
// ---------------------------------------------------------------------------
__device__ __half g_h1  [(size_t)16384 * 4096];
__device__ __half g_pq  [(size_t)16384 * 2048];
__device__ __half g_t2p [(size_t)16384 * 2048];   // pre-LN t2 (fp16)
__device__ __half g_t2q [(size_t)16384 * 2048];   // post-LN tanh (fp16)
__device__ __half g_amph[(size_t)16384 * 1024];   // amp (fp16)
__device__ __half g_phh [(size_t)16384 * 1024];   // phase (fp16)
__device__ __half g_qs  [(size_t)16384 * 1024];
__device__ __half g_w2  [(size_t)2048 * 4096];
__device__ __half g_w3  [(size_t)1024 * 2048];
__device__ __half g_pw2 [(size_t)1024 * 2048];
__device__ __half g_wvth[(size_t)1024 * 1024], g_wvtl[(size_t)1024 * 1024];
__device__ __half g_woh [(size_t)1024 * 1024], g_wol [(size_t)1024 * 1024];
__device__ float  g_wff [(size_t)1024 * 1024];
__device__ __half g_wf  [(size_t)1024 * 1024];
__device__ float  g_bfused[1024];
__device__ float  g_bzero[1024];

// ---------------------------------------------------------------------------
// Main GEMM (1-term): C[m,n] = sum_k A[m,k]*W[n,k] + bias[n]
// CTA 256x128, 8 warps 4(m)x2(n), warp tile 64x64, 4-stage ring.
// EPI: 0 = fp32 store; 2 = fp16 store;
//      3 = merged two-GEMM, fp16 store (z==1 -> second set + tanh)
// ---------------------------------------------------------------------------
template<int EPI>
__global__ __launch_bounds__(256, 1)
void gemm_f16(const __half* __restrict__ A, const __half* __restrict__ W,
              const float* __restrict__ bias, float* __restrict__ Cf,
              __half* __restrict__ Chf,
              const __half* A2, const __half* W2p,
              const float* bias2, __half* Chf2,
              int N, int K)
{
    extern __shared__ char smem[];
    const uint32_t sb = smem_u32(smem);
    const uint32_t TILES = (sb + 1023u) & ~1023u;
    const uint32_t STG = 49152;   // A 32KB | W 16KB

    bool second = false;
    if (EPI == 3 && blockIdx.z == 1) {
        second = true;
        A = A2; W = W2p; bias = bias2; Chf = Chf2;
    }

    const int tid = threadIdx.x, wid = tid >> 5, lane = tid & 31;
    const int bm = blockIdx.y * 256, bn = blockIdx.x * 128;
    const int warp_m = wid & 3, warp_n = wid >> 2;
    const int nC = K >> 6;

    auto load_chunk = [&](int ci, int s) {
        const int k0 = ci << 6;
        const uint32_t stg = TILES + s * STG;
#pragma unroll
        for (int t = 0; t < 8; t++) {
            const int g = tid + t * 256;
            const int row = g >> 3;
            const int col8 = (g & 7) * 8;
            const uint32_t so = swz((uint32_t)(row * 128 + col8 * 2));
            cp16(stg + so, A + (size_t)(bm + row) * K + k0 + col8);
        }
#pragma unroll
        for (int t = 0; t < 4; t++) {
            const int g = tid + t * 256;
            const int row = g >> 3;
            const int col8 = (g & 7) * 8;
            const uint32_t so = swz((uint32_t)(row * 128 + col8 * 2));
            cp16(stg + 32768 + so, W + (size_t)(bn + row) * K + k0 + col8);
        }
        CP_COMMIT();
    };

    const uint32_t mA = warp_m * 64 + ((lane >> 3) & 1) * 8 + (lane & 7);
    const uint32_t kA = (lane >> 4) * 8;
    const uint32_t nB = warp_n * 64 + (lane >> 4) * 8 + (lane & 7);
    const uint32_t kB = ((lane >> 3) & 1) * 8;

    float acc[4][8][4];
#pragma unroll
    for (int i = 0; i < 4; i++)
#pragma unroll
        for (int j = 0; j < 8; j++)
#pragma unroll
            for (int e = 0; e < 4; e++) acc[i][j][e] = 0.f;

    load_chunk(0, 0);
    if (nC > 1) load_chunk(1, 1);
    if (nC > 2) load_chunk(2, 2);

    for (int i = 0; i < nC; i++) {
        const int s = i & 3;
        if (i < nC - 2)       { CP_WAIT(2); }
        else if (i == nC - 2) { CP_WAIT(1); }
        else                  { CP_WAIT(0); }
        __syncthreads();
        // Stage (i+3)&3 was consumed in iter i-1; barrier proves all warps past it.
        if (i + 3 < nC) load_chunk(i + 3, (i + 3) & 3);

        const uint32_t stg = TILES + s * STG;
        const uint32_t Ab = stg, Bb = stg + 32768;

#pragma unroll
        for (int ks = 0; ks < 4; ks++) {
            uint32_t bh[4][4];
#pragma unroll
            for (int g = 0; g < 4; g++) {
                const uint32_t oB = swz((nB + g * 16) * 128 + (ks * 16 + kB) * 2);
                ldsm4(bh[g], Bb + oB);
            }
#pragma unroll
            for (int mi = 0; mi < 4; mi++) {
                const uint32_t oA = swz((mA + mi * 16) * 128 + (ks * 16 + kA) * 2);
                uint32_t ah[4];
                ldsm4(ah, Ab + oA);
#pragma unroll
                for (int ni = 0; ni < 8; ni++)
                    mma_f16(acc[mi][ni], ah, &bh[ni >> 1][(ni & 1) * 2]);
            }
        }
    }

    const int r0l   = lane >> 2;
    const int cpair = (lane & 3) * 2;
    const int mbase = bm + warp_m * 64;
    const int nbase = bn + warp_n * 64;

#pragma unroll
    for (int mi = 0; mi < 4; mi++) {
        const int row0 = mbase + mi * 16 + r0l;
        const int row1 = row0 + 8;
#pragma unroll
        for (int ni = 0; ni < 8; ni++) {
            const int col = nbase + ni * 8 + cpair;
            const float2 bv = *(const float2*)&bias[col];
            float v0 = acc[mi][ni][0] + bv.x;
            float v1 = acc[mi][ni][1] + bv.y;
            float v2 = acc[mi][ni][2] + bv.x;
            float v3 = acc[mi][ni][3] + bv.y;
            if (EPI == 3 && second) {
                v0 = tanhf(v0); v1 = tanhf(v1); v2 = tanhf(v2); v3 = tanhf(v3);
            }
            if (EPI == 0) {
                *(float2*)&Cf[(size_t)row0 * N + col] = make_float2(v0, v1);
                *(float2*)&Cf[(size_t)row1 * N + col] = make_float2(v2, v3);
            } else {
                *(uint32_t*)&Chf[(size_t)row0 * N + col] = pack2h(v0, v1);
                *(uint32_t*)&Chf[(size_t)row1 * N + col] = pack2h(v2, v3);
            }
        }
    }
}

// ---------------------------------------------------------------------------
// Precompute GEMM (3-term, 2-plane both operands): Wfused = Wout @ Wv^T
// CTA 128x128, warp 64x32, 3-stage ring (safe refill i+2).
// ---------------------------------------------------------------------------
__global__ __launch_bounds__(256, 1)
void gemm3_pre(const __half* __restrict__ Ah, const __half* __restrict__ Al,
               const __half* __restrict__ Wh, const __half* __restrict__ Wl,
               const float* __restrict__ bias, float* __restrict__ Cf,
               int N, int K)
{
    extern __shared__ char smem[];
    const uint32_t sb = smem_u32(smem);
    const uint32_t TILES = (sb + 1023u) & ~1023u;
    const uint32_t STG = 65536;

    const int tid = threadIdx.x, wid = tid >> 5, lane = tid & 31;
    const int bm = blockIdx.y * 128, bn = blockIdx.x * 128;
    const int warp_m = wid & 1, warp_n = wid >> 1;
    const int nC = K >> 6;

    auto load_chunk = [&](int ci, int s) {
        const int k0 = ci << 6;
        const uint32_t stg = TILES + s * STG;
#pragma unroll
        for (int t = 0; t < 4; t++) {
            const int g = tid + t * 256;
            const int row = g >> 3;
            const int col8 = (g & 7) * 8;
            const uint32_t so = swz((uint32_t)(row * 128 + col8 * 2));
            const size_t ia = (size_t)(bm + row) * K + k0 + col8;
            const size_t ib = (size_t)(bn + row) * K + k0 + col8;
            cp16(stg + so,         Ah + ia);
            cp16(stg + 16384 + so, Al + ia);
            cp16(stg + 32768 + so, Wh + ib);
            cp16(stg + 49152 + so, Wl + ib);
        }
        CP_COMMIT();
    };

    const uint32_t mA = warp_m * 64 + ((lane >> 3) & 1) * 8 + (lane & 7);
    const uint32_t kA = (lane >> 4) * 8;
    const uint32_t nB = warp_n * 32 + (lane >> 4) * 8 + (lane & 7);
    const uint32_t kB = ((lane >> 3) & 1) * 8;

    float acc[4][4][4];
#pragma unroll
    for (int i = 0; i < 4; i++)
#pragma unroll
        for (int j = 0; j < 4; j++)
#pragma unroll
            for (int e = 0; e < 4; e++) acc[i][j][e] = 0.f;

    load_chunk(0, 0);
    if (nC > 1) load_chunk(1, 1);

    for (int i = 0; i < nC; i++) {
        const int s = i - (i / 3) * 3;
        if (i < nC - 1) { CP_WAIT(1); } else { CP_WAIT(0); }
        __syncthreads();
        if (i + 2 < nC) load_chunk(i + 2, (i + 2) - ((i + 2) / 3) * 3);

        const uint32_t stg = TILES + s * STG;
        const uint32_t Ahb = stg, Alb = stg + 16384;
        const uint32_t Bhb = stg + 32768, Blb = stg + 49152;

#pragma unroll
        for (int ks = 0; ks < 4; ks++) {
            const uint32_t oB0 = swz(nB * 128 + (ks * 16 + kB) * 2);
            const uint32_t oB1 = swz((nB + 16) * 128 + (ks * 16 + kB) * 2);
            uint32_t bh0[4], bh1[4], bl0[4], bl1[4];
            ldsm4(bh0, Bhb + oB0);
            ldsm4(bh1, Bhb + oB1);
            ldsm4(bl0, Blb + oB0);
            ldsm4(bl1, Blb + oB1);
#pragma unroll
            for (int mi = 0; mi < 4; mi++) {
                const uint32_t oA = swz((mA + mi * 16) * 128 + (ks * 16 + kA) * 2);
                uint32_t ah[4], al[4];
                ldsm4(ah, Ahb + oA);
                ldsm4(al, Alb + oA);
#pragma unroll
                for (int ni = 0; ni < 4; ni++) {
                    const uint32_t* bhp = (ni < 2) ? &bh0[(ni & 1) * 2] : &bh1[(ni & 1) * 2];
                    const uint32_t* blp = (ni < 2) ? &bl0[(ni & 1) * 2] : &bl1[(ni & 1) * 2];
                    mma_f16(acc[mi][ni], ah, bhp);
                    mma_f16(acc[mi][ni], ah, blp);
                    mma_f16(acc[mi][ni], al, bhp);
                }
            }
        }
        __syncthreads();
    }

    const int r0l   = lane >> 2;
    const int cpair = (lane & 3) * 2;
    const int mbase = bm + warp_m * 64;
    const int nbase = bn + warp_n * 32;
#pragma unroll
    for (int mi = 0; mi < 4; mi++) {
        const int row0 = mbase + mi * 16 + r0l;
        const int row1 = row0 + 8;
#pragma unroll
        for (int ni = 0; ni < 4; ni++) {
            const int col = nbase + ni * 8 + cpair;
            const float2 bv = *(const float2*)&bias[col];
            *(float2*)&Cf[(size_t)row0 * N + col] =
                make_float2(acc[mi][ni][0] + bv.x, acc[mi][ni][1] + bv.y);
            *(float2*)&Cf[(size_t)row1 * N + col] =
                make_float2(acc[mi][ni][2] + bv.x, acc[mi][ni][3] + bv.y);
        }
    }
}

// ---------------------------------------------------------------------------
DEVI float2 block_reduce2(float2 v, float2* sbuf) {
    const int lane = threadIdx.x & 31, wid = threadIdx.x >> 5;
#pragma unroll
    for (int o = 16; o > 0; o >>= 1) {
        v.x += __shfl_xor_sync(0xffffffffu, v.x, o);
        v.y += __shfl_xor_sync(0xffffffffu, v.y, o);
    }
    if (lane == 0) sbuf[wid] = v;
    __syncthreads();
    if (wid == 0) {
        float2 t = (lane < 8) ? sbuf[lane] : make_float2(0.f, 0.f);
#pragma unroll
        for (int o = 4; o > 0; o >>= 1) {
            t.x += __shfl_xor_sync(0xffffffffu, t.x, o);
            t.y += __shfl_xor_sync(0xffffffffu, t.y, o);
        }
        if (lane == 0) sbuf[0] = t;
    }
    __syncthreads();
    float2 r = sbuf[0];
    __syncthreads();
    return r;
}

// ---------------------------------------------------------------------------
// Layer-1: 8 rows/block, weights cached in smem; fp16 outputs
// ---------------------------------------------------------------------------
__global__ __launch_bounds__(256)
void layer1_k(const float* __restrict__ x,
              const float* __restrict__ aW1, const float* __restrict__ ab1,
              const float* __restrict__ ag1, const float* __restrict__ abe1,
              const float* __restrict__ pW1, const float* __restrict__ pb1,
              const float* __restrict__ pg1, const float* __restrict__ pbe1,
              __half* __restrict__ h1, __half* __restrict__ pq)
{
    extern __shared__ float sw[];
    float2* W  = (float2*)sw;
    float*  Bb = sw + 8192;
    float*  Gg = sw + 12288;
    float*  Be = sw + 16384;
    __shared__ float2 sbuf[8];

    const int tid = threadIdx.x;
    const int rb = blockIdx.x * 8;

    for (int i = tid; i < 4096; i += 256) {
        W[i]  = ((const float2*)aW1)[i];
        Bb[i] = ab1[i]; Gg[i] = ag1[i]; Be[i] = abe1[i];
    }
    __syncthreads();
    for (int r = 0; r < 8; r++) {
        const int b = rb + r;
        const float x0 = x[2 * b], x1 = x[2 * b + 1];
        float2 ss = make_float2(0.f, 0.f);
#pragma unroll
        for (int t = 0; t < 16; t++) {
            const int i = tid + t * 256;
            const float v = fmaf(W[i].y, x1, fmaf(W[i].x, x0, Bb[i]));
            ss.x += v; ss.y += v * v;
        }
        const float2 rr = block_reduce2(ss, sbuf);
        const float m = rr.x * (1.f / 4096.f);
        const float rstd = rsqrtf(rr.y * (1.f / 4096.f) - m * m + 1e-5f);
#pragma unroll
        for (int t = 0; t < 16; t++) {
            const int i = tid + t * 256;
            const float v = fmaf(W[i].y, x1, fmaf(W[i].x, x0, Bb[i]));
            const float hh = (v - m) * rstd * Gg[i] + Be[i];
            const float g = 0.5f * hh * (1.f + erff(hh * 0.70710678118654752f));
            h1[(size_t)b * 4096 + i] = __float2half_rn(g);
        }
    }
    __syncthreads();

    for (int i = tid; i < 2048; i += 256) {
        W[i]  = ((const float2*)pW1)[i];
        Bb[i] = pb1[i]; Gg[i] = pg1[i]; Be[i] = pbe1[i];
    }
    __syncthreads();
    for (int r = 0; r < 8; r++) {
        const int b = rb + r;
        const float x0 = x[2 * b], x1 = x[2 * b + 1];
        float2 ss = make_float2(0.f, 0.f);
#pragma unroll
        for (int t = 0; t < 8; t++) {
            const int i = tid + t * 256;
            const float v = fmaf(W[i].y, x1, fmaf(W[i].x, x0, Bb[i]));
            ss.x += v; ss.y += v * v;
        }
        const float2 rr = block_reduce2(ss, sbuf);
        const float m = rr.x * (1.f / 2048.f);
        const float rstd = rsqrtf(rr.y * (1.f / 2048.f) - m * m + 1e-5f);
#pragma unroll
        for (int t = 0; t < 8; t++) {
            const int i = tid + t * 256;
            const float v = fmaf(W[i].y, x1, fmaf(W[i].x, x0, Bb[i]));
            const float hh = (v - m) * rstd * Gg[i] + Be[i];
            pq[(size_t)b * 2048 + i] = __float2half_rn(hh / (1.f + expf(-hh)));
        }
    }
}

// ---------------------------------------------------------------------------
// LN + tanh over row of 2048, fp16 in (one uint4/thread) -> fp16 out
// ---------------------------------------------------------------------------
__global__ __launch_bounds__(256)
void ln_tanh_kernel(const __half* __restrict__ in,
                    const float* __restrict__ g, const float* __restrict__ be,
                    __half* __restrict__ oq)
{
    __shared__ float2 sbuf[8];
    const int b = blockIdx.x, tid = threadIdx.x;
    const uint4 raw = *(const uint4*)(in + (size_t)b * 2048 + tid * 8);
    float va[8];
    {
        const __half2* hp = (const __half2*)&raw;
#pragma unroll
        for (int j = 0; j < 4; j++) {
            const float2 f = __half22float2(hp[j]);
            va[2 * j] = f.x; va[2 * j + 1] = f.y;
        }
    }
    float2 ss = make_float2(0.f, 0.f);
#pragma unroll
    for (int j = 0; j < 8; j++) { ss.x += va[j]; ss.y += va[j] * va[j]; }
    const float2 r = block_reduce2(ss, sbuf);
    const float m = r.x * (1.f / 2048.f);
    const float rstd = rsqrtf(r.y * (1.f / 2048.f) - m * m + 1e-5f);

    const int i0 = tid * 8;
    const float4 g0 = *(const float4*)&g[i0];
    const float4 g1 = *(const float4*)&g[i0 + 4];
    const float4 e0 = *(const float4*)&be[i0];
    const float4 e1 = *(const float4*)&be[i0 + 4];
    const float gv[8] = {g0.x, g0.y, g0.z, g0.w, g1.x, g1.y, g1.z, g1.w};
    const float ev[8] = {e0.x, e0.y, e0.z, e0.w, e1.x, e1.y, e1.z, e1.w};
    uint4 outw;
    uint32_t* ow = (uint32_t*)&outw;
#pragma unroll
    for (int j = 0; j < 4; j++) {
        const float v0 = tanhf((va[2 * j]     - m) * rstd * gv[2 * j]     + ev[2 * j]);
        const float v1 = tanhf((va[2 * j + 1] - m) * rstd * gv[2 * j + 1] + ev[2 * j + 1]);
        ow[j] = pack2h(v0, v1);
    }
    *(uint4*)(oq + (size_t)b * 2048 + i0) = outw;
}

// ---------------------------------------------------------------------------
// qs mixing: fp16 amp/ph in (4/thread) -> fp16 qs
// ---------------------------------------------------------------------------
__global__ __launch_bounds__(256)
void qs_kernel(const __half* __restrict__ amp, const __half* __restrict__ phv,
               const float* __restrict__ rf, const float* __restrict__ rp,
               __half* __restrict__ q)
{
    const int i4 = (blockIdx.x * 256 + threadIdx.x) * 4;
    const int q0 = i4 & 1023;
    const uint2 ar = *(const uint2*)(amp + i4);
    const uint2 pr = *(const uint2*)(phv + i4);
    const __half2* ah = (const __half2*)&ar;
    const __half2* ph = (const __half2*)&pr;
    const float2 a01 = __half22float2(ah[0]), a23 = __half22float2(ah[1]);
    const float2 p01 = __half22float2(ph[0]), p23 = __half22float2(ph[1]);
    const float av[4] = {a01.x, a01.y, a23.x, a23.y};
    const float pv[4] = {p01.x, p01.y, p23.x, p23.y};
    const float* rfb = rf + 4 * 1024 * 3;
    const float* rpb = rp + 4 * 1024 * 3;
    uint32_t ow[2];
    float qv[4];
#pragma unroll
    for (int j = 0; j < 4; j++) {
        const int qq = q0 + j;
        const float rx = sinf(fmaf(av[j], rfb[3 * qq + 0], rpb[3 * qq + 0]));
        const float ry = cosf(fmaf(pv[j], rfb[3 * qq + 1], rpb[3 * qq + 1]));
        const float rz = tanhf(rpb[3 * qq + 2]);
        qv[j] = (rx + ry + rz) * (1.f / 3.f);
    }
    ow[0] = pack2h(qv[0], qv[1]);
    ow[1] = pack2h(qv[2], qv[3]);
    *(uint2*)(q + i4) = make_uint2(ow[0], ow[1]);
}

// ---------------------------------------------------------------------------
__global__ __launch_bounds__(256)
void wconv_kernel(const float* __restrict__ s, __half* __restrict__ h, int n)
{
    const int i = blockIdx.x * 256 + threadIdx.x;
    if (i < n) h[i] = __float2half_rn(s[i]);
}

__global__ __launch_bounds__(256)
void wsplit_kernel(const float* __restrict__ s,
                   __half* __restrict__ h, __half* __restrict__ l, int n)
{
    const int i = blockIdx.x * 256 + threadIdx.x;
    if (i < n) {
        __half hh, ll;
        split_h(s[i], hh, ll);
        h[i] = hh; l[i] = ll;
    }
}

__global__ void tsplit_kernel(const float* __restrict__ W,
                              __half* __restrict__ th, __half* __restrict__ tl)
{
    __shared__ float tile[32][33];
    const int tx = threadIdx.x, ty = threadIdx.y;
    const int bx = blockIdx.x * 32, by = blockIdx.y * 32;
#pragma unroll
    for (int r = 0; r < 4; r++)
        tile[ty * 4 + r][tx] = W[(size_t)(by + ty * 4 + r) * 1024 + bx + tx];
    __syncthreads();
#pragma unroll
    for (int r = 0; r < 4; r++) {
        const float v = tile[tx][ty * 4 + r];
        __half h, l; split_h(v, h, l);
        const size_t o = (size_t)(bx + ty * 4 + r) * 1024 + by + tx;
        th[o] = h; tl[o] = l;
    }
}

__global__ __launch_bounds__(256)
void bfuse_kernel(const float* __restrict__ Wout, const float* __restrict__ bv,
                  const float* __restrict__ bout, float* __restrict__ bf)
{
    __shared__ float2 sbuf[8];
    const int o = blockIdx.x, tid = threadIdx.x;
    float s = 0.f;
#pragma unroll
    for (int t = 0; t < 4; t++) {
        const int i = tid + t * 256;
        s = fmaf(Wout[(size_t)o * 1024 + i], bv[i], s);
    }
    const float2 r = block_reduce2(make_float2(s, 0.f), sbuf);
    if (tid == 0) bf[o] = r.x + bout[o];
}

// ---------------------------------------------------------------------------
extern "C" void kernel_launch(void* const* d_in, const int* in_sizes, int n_in,
                              void* d_out, int out_size)
{
    const float* x    = (const float*)d_in[0];
    const float* aW1  = (const float*)d_in[1];
    const float* ab1  = (const float*)d_in[2];
    const float* ag1  = (const float*)d_in[3];
    const float* abe1 = (const float*)d_in[4];
    const float* aW2  = (const float*)d_in[5];
    const float* ab2  = (const float*)d_in[6];
    const float* ag2  = (const float*)d_in[7];
    const float* abe2 = (const float*)d_in[8];
    const float* aW3  = (const float*)d_in[9];
    const float* ab3  = (const float*)d_in[10];
    const float* pW1  = (const float*)d_in[11];
    const float* pb1  = (const float*)d_in[12];
    const float* pg1  = (const float*)d_in[13];
    const float* pbe1 = (const float*)d_in[14];
    const float* pW2  = (const float*)d_in[15];
    const float* pb2  = (const float*)d_in[16];
    const float* rf   = (const float*)d_in[17];
    const float* rp   = (const float*)d_in[18];
    const float* winV = (const float*)d_in[19] + (size_t)2048 * 1024;
    const float* binV = (const float*)d_in[20] + 2048;
    const float* wout = (const float*)d_in[21];
    const float* bout = (const float*)d_in[22];
    float* out = (float*)d_out;

    __half *h1, *pq, *t2p, *t2q, *amph, *phh, *qs;
    __half *w2, *w3, *pw2, *wvth, *wvtl, *woh, *wol, *wf;
    float *wff, *bfused, *bzero;
    cudaGetSymbolAddress((void**)&h1, g_h1);
    cudaGetSymbolAddress((void**)&pq, g_pq);
    cudaGetSymbolAddress((void**)&t2p, g_t2p);
    cudaGetSymbolAddress((void**)&t2q, g_t2q);
    cudaGetSymbolAddress((void**)&amph, g_amph);
    cudaGetSymbolAddress((void**)&phh, g_phh);
    cudaGetSymbolAddress((void**)&qs, g_qs);
    cudaGetSymbolAddress((void**)&w2, g_w2);
    cudaGetSymbolAddress((void**)&w3, g_w3);
    cudaGetSymbolAddress((void**)&pw2, g_pw2);
    cudaGetSymbolAddress((void**)&wvth, g_wvth); cudaGetSymbolAddress((void**)&wvtl, g_wvtl);
    cudaGetSymbolAddress((void**)&woh, g_woh); cudaGetSymbolAddress((void**)&wol, g_wol);
    cudaGetSymbolAddress((void**)&wff, g_wff);
    cudaGetSymbolAddress((void**)&wf, g_wf);
    cudaGetSymbolAddress((void**)&bfused, g_bfused);
    cudaGetSymbolAddress((void**)&bzero, g_bzero);

    const int SMEMB = 1024 + 4 * 49152;
    cudaFuncSetAttribute(gemm_f16<0>, cudaFuncAttributeMaxDynamicSharedMemorySize, SMEMB);
    cudaFuncSetAttribute(gemm_f16<2>, cudaFuncAttributeMaxDynamicSharedMemorySize, SMEMB);
    cudaFuncSetAttribute(gemm_f16<3>, cudaFuncAttributeMaxDynamicSharedMemorySize, SMEMB);
    const int SMEMP = 1024 + 3 * 65536;
    cudaFuncSetAttribute(gemm3_pre, cudaFuncAttributeMaxDynamicSharedMemorySize, SMEMP);
    const int L1SMEM = 81920;
    cudaFuncSetAttribute(layer1_k, cudaFuncAttributeMaxDynamicSharedMemorySize, L1SMEM);

    const int M = 16384;

    // W2 conversion first, then layer1
    wconv_kernel<<<(2048 * 4096) / 256, 256>>>(aW2, w2, 2048 * 4096);
    layer1_k<<<M / 8, 256, L1SMEM>>>(x, aW1, ab1, ag1, abe1, pW1, pb1, pg1, pbe1,
                                     h1, pq);
    wconv_kernel<<<(1024 * 2048) / 256, 256>>>(aW3, w3, 1024 * 2048);

    // GEMM1: t2pre = h1 @ W2^T + b2  (fp16 out)
    gemm_f16<2><<<dim3(16, 64), 256, SMEMB>>>(h1, w2, ab2, nullptr, t2p,
                                              nullptr, nullptr, nullptr, nullptr,
                                              2048, 4096);

    // Fused-weight precompute
    wconv_kernel<<<(1024 * 2048) / 256, 256>>>(pW2, pw2, 1024 * 2048);
    tsplit_kernel<<<dim3(32, 32), dim3(32, 8)>>>(winV, wvth, wvtl);
    wsplit_kernel<<<(1024 * 1024) / 256, 256>>>(wout, woh, wol, 1024 * 1024);
    gemm3_pre<<<dim3(8, 8), 256, SMEMP>>>(woh, wol, wvth, wvtl, bzero, wff,
                                          1024, 1024);
    bfuse_kernel<<<1024, 256>>>(wout, binV, bout, bfused);
    wconv_kernel<<<(1024 * 1024) / 256, 256>>>(wff, wf, 1024 * 1024);

    ln_tanh_kernel<<<M, 256>>>(t2p, ag2, abe2, t2q);

    // merged GEMM2 (amp) + GEMM3 (phase, tanh), fp16 outputs
    gemm_f16<3><<<dim3(8, 64, 2), 256, SMEMB>>>(t2q, w3, ab3, nullptr, amph,
                                                pq, pw2, pb2, phh,
                                                1024, 2048);

    qs_kernel<<<(M * 1024) / 1024, 256>>>(amph, phh, rf, rp, qs);

    // out = qs @ Wfused^T + bfused
    gemm_f16<0><<<dim3(8, 64), 256, SMEMB>>>(qs, wf, bfused, out, nullptr,
                                             nullptr, nullptr, nullptr, nullptr,
                                             1024, 1024);
}

// round 15
// speedup vs baseline: 1.1605x; 1.0113x over previous
#include <cuda_runtime.h>
#include <cuda_fp16.h>
#include <cstdint>

// ===========================================================================
// B=16384, Q=1024, F=2. mma.sync m16n8k16 fp16 single-plane (1 MMA term).
// Main GEMM: CTA 256x128, warp 64x64, K-chunk 64, 4-stage cp.async ring.
// GEMM2+GEMM3 merged via gridDim.z; GEMM4+GEMM5 fused algebraically.
// Elementwise tail uses MUFU approximations (tanh.approx / sin.approx /
// cos.approx / ex2) — error at/below the fp16 storage rounding.
// ===========================================================================

#define DEVI __device__ __forceinline__

DEVI uint32_t smem_u32(const void* p) {
    uint32_t r;
    asm("{ .reg .u64 t; cvta.to.shared.u64 t, %1; cvt.u32.u64 %0, t; }"
        : "=r"(r) : "l"(p));
    return r;
}
DEVI uint32_t swz(uint32_t x) { return x ^ ((x >> 3) & 0x70); }

DEVI void cp16(uint32_t dst, const void* src) {
    asm volatile("cp.async.cg.shared.global [%0], [%1], 16;"
                 :: "r"(dst), "l"(src));
}
#define CP_COMMIT() asm volatile("cp.async.commit_group;" ::: "memory")
#define CP_WAIT(n)  asm volatile("cp.async.wait_group %0;" :: "n"(n) : "memory")

DEVI void ldsm4(uint32_t* r, uint32_t a) {
    asm volatile("ldmatrix.sync.aligned.m8n8.x4.shared.b16 {%0,%1,%2,%3}, [%4];"
                 : "=r"(r[0]), "=r"(r[1]), "=r"(r[2]), "=r"(r[3]) : "r"(a));
}
DEVI void mma_f16(float* d, const uint32_t* a, const uint32_t* b) {
    asm volatile("mma.sync.aligned.m16n8k16.row.col.f32.f16.f16.f32 "
                 "{%0,%1,%2,%3},{%4,%5,%6,%7},{%8,%9},{%0,%1,%2,%3};"
                 : "+f"(d[0]), "+f"(d[1]), "+f"(d[2]), "+f"(d[3])
                 : "r"(a[0]), "r"(a[1]), "r"(a[2]), "r"(a[3]),
                   "r"(b[0]), "r"(b[1]));
}

DEVI float tanh_fast(float x) {
    float y;
    asm("tanh.approx.f32 %0, %1;" : "=f"(y) : "f"(x));
    return y;
}
DEVI float sin_fast(float x) {
    float y;
    asm("sin.approx.f32 %0, %1;" : "=f"(y) : "f"(x));
    return y;
}
DEVI float cos_fast(float x) {
    float y;
    asm("cos.approx.f32 %0, %1;" : "=f"(y) : "f"(x));
    return y;
}

DEVI void split_h(float v, __half& h, __half& l) {
    h = __float2half_rn(v);
    l = __float2half_rn(v - __half2float(h));
}
DEVI uint32_t pack2h(float a, float b) {
    __half2 p = __floats2half2_rn(a, b);
    return *(uint32_t*)&p;
}

// ---------------------------------------------------------------------------
// Scratch
// ---------------------------------------------------------------------------
__device__ __half g_h1  [(size_t)16384 * 4096];
__device__ __half g_pq  [(size_t)16384 * 2048];
__device__ __half g_t2p [(size_t)16384 * 2048];   // pre-LN t2 (fp16)
__device__ __half g_t2q [(size_t)16384 * 2048];   // post-LN tanh (fp16)
__device__ __half g_amph[(size_t)16384 * 1024];
__device__ __half g_phh [(size_t)16384 * 1024];
__device__ __half g_qs  [(size_t)16384 * 1024];
__device__ __half g_w2  [(size_t)2048 * 4096];
__device__ __half g_w3  [(size_t)1024 * 2048];
__device__ __half g_pw2 [(size_t)1024 * 2048];
__device__ __half g_wvth[(size_t)1024 * 1024], g_wvtl[(size_t)1024 * 1024];
__device__ __half g_woh [(size_t)1024 * 1024], g_wol [(size_t)1024 * 1024];
__device__ float  g_wff [(size_t)1024 * 1024];
__device__ __half g_wf  [(size_t)1024 * 1024];
__device__ float  g_bfused[1024];
__device__ float  g_bzero[1024];
__device__ float4 g_rtab[1024];   // (f0, p0, f1, p1) per q
__device__ float  g_rz  [1024];   // tanh(rot_phase[-1,q,2]) per q

// ---------------------------------------------------------------------------
// Main GEMM (1-term): C[m,n] = sum_k A[m,k]*W[n,k] + bias[n]
// CTA 256x128, 8 warps 4(m)x2(n), warp tile 64x64, 4-stage ring.
// EPI: 0 = fp32 store; 2 = fp16 store;
//      3 = merged two-GEMM, fp16 store (z==1 -> second set + tanh)
// ---------------------------------------------------------------------------
template<int EPI>
__global__ __launch_bounds__(256, 1)
void gemm_f16(const __half* __restrict__ A, const __half* __restrict__ W,
              const float* __restrict__ bias, float* __restrict__ Cf,
              __half* __restrict__ Chf,
              const __half* A2, const __half* W2p,
              const float* bias2, __half* Chf2,
              int N, int K)
{
    extern __shared__ char smem[];
    const uint32_t sb = smem_u32(smem);
    const uint32_t TILES = (sb + 1023u) & ~1023u;
    const uint32_t STG = 49152;   // A 32KB | W 16KB

    bool second = false;
    if (EPI == 3 && blockIdx.z == 1) {
        second = true;
        A = A2; W = W2p; bias = bias2; Chf = Chf2;
    }

    const int tid = threadIdx.x, wid = tid >> 5, lane = tid & 31;
    const int bm = blockIdx.y * 256, bn = blockIdx.x * 128;
    const int warp_m = wid & 3, warp_n = wid >> 2;
    const int nC = K >> 6;

    auto load_chunk = [&](int ci, int s) {
        const int k0 = ci << 6;
        const uint32_t stg = TILES + s * STG;
#pragma unroll
        for (int t = 0; t < 8; t++) {
            const int g = tid + t * 256;
            const int row = g >> 3;
            const int col8 = (g & 7) * 8;
            const uint32_t so = swz((uint32_t)(row * 128 + col8 * 2));
            cp16(stg + so, A + (size_t)(bm + row) * K + k0 + col8);
        }
#pragma unroll
        for (int t = 0; t < 4; t++) {
            const int g = tid + t * 256;
            const int row = g >> 3;
            const int col8 = (g & 7) * 8;
            const uint32_t so = swz((uint32_t)(row * 128 + col8 * 2));
            cp16(stg + 32768 + so, W + (size_t)(bn + row) * K + k0 + col8);
        }
        CP_COMMIT();
    };

    const uint32_t mA = warp_m * 64 + ((lane >> 3) & 1) * 8 + (lane & 7);
    const uint32_t kA = (lane >> 4) * 8;
    const uint32_t nB = warp_n * 64 + (lane >> 4) * 8 + (lane & 7);
    const uint32_t kB = ((lane >> 3) & 1) * 8;

    float acc[4][8][4];
#pragma unroll
    for (int i = 0; i < 4; i++)
#pragma unroll
        for (int j = 0; j < 8; j++)
#pragma unroll
            for (int e = 0; e < 4; e++) acc[i][j][e] = 0.f;

    load_chunk(0, 0);
    if (nC > 1) load_chunk(1, 1);
    if (nC > 2) load_chunk(2, 2);

    for (int i = 0; i < nC; i++) {
        const int s = i & 3;
        if (i < nC - 2)       { CP_WAIT(2); }
        else if (i == nC - 2) { CP_WAIT(1); }
        else                  { CP_WAIT(0); }
        __syncthreads();
        // Stage (i+3)&3 was consumed in iter i-1; barrier proves all warps past it.
        if (i + 3 < nC) load_chunk(i + 3, (i + 3) & 3);

        const uint32_t stg = TILES + s * STG;
        const uint32_t Ab = stg, Bb = stg + 32768;

#pragma unroll
        for (int ks = 0; ks < 4; ks++) {
            uint32_t bh[4][4];
#pragma unroll
            for (int g = 0; g < 4; g++) {
                const uint32_t oB = swz((nB + g * 16) * 128 + (ks * 16 + kB) * 2);
                ldsm4(bh[g], Bb + oB);
            }
#pragma unroll
            for (int mi = 0; mi < 4; mi++) {
                const uint32_t oA = swz((mA + mi * 16) * 128 + (ks * 16 + kA) * 2);
                uint32_t ah[4];
                ldsm4(ah, Ab + oA);
#pragma unroll
                for (int ni = 0; ni < 8; ni++)
                    mma_f16(acc[mi][ni], ah, &bh[ni >> 1][(ni & 1) * 2]);
            }
        }
    }

    const int r0l   = lane >> 2;
    const int cpair = (lane & 3) * 2;
    const int mbase = bm + warp_m * 64;
    const int nbase = bn + warp_n * 64;

#pragma unroll
    for (int mi = 0; mi < 4; mi++) {
        const int row0 = mbase + mi * 16 + r0l;
        const int row1 = row0 + 8;
#pragma unroll
        for (int ni = 0; ni < 8; ni++) {
            const int col = nbase + ni * 8 + cpair;
            const float2 bv = *(const float2*)&bias[col];
            float v0 = acc[mi][ni][0] + bv.x;
            float v1 = acc[mi][ni][1] + bv.y;
            float v2 = acc[mi][ni][2] + bv.x;
            float v3 = acc[mi][ni][3] + bv.y;
            if (EPI == 3 && second) {
                v0 = tanh_fast(v0); v1 = tanh_fast(v1);
                v2 = tanh_fast(v2); v3 = tanh_fast(v3);
            }
            if (EPI == 0) {
                *(float2*)&Cf[(size_t)row0 * N + col] = make_float2(v0, v1);
                *(float2*)&Cf[(size_t)row1 * N + col] = make_float2(v2, v3);
            } else {
                *(uint32_t*)&Chf[(size_t)row0 * N + col] = pack2h(v0, v1);
                *(uint32_t*)&Chf[(size_t)row1 * N + col] = pack2h(v2, v3);
            }
        }
    }
}

// ---------------------------------------------------------------------------
// Precompute GEMM (3-term, 2-plane both operands): Wfused = Wout @ Wv^T
// CTA 128x128, warp 64x32, 3-stage ring (safe refill i+2).
// ---------------------------------------------------------------------------
__global__ __launch_bounds__(256, 1)
void gemm3_pre(const __half* __restrict__ Ah, const __half* __restrict__ Al,
               const __half* __restrict__ Wh, const __half* __restrict__ Wl,
               const float* __restrict__ bias, float* __restrict__ Cf,
               int N, int K)
{
    extern __shared__ char smem[];
    const uint32_t sb = smem_u32(smem);
    const uint32_t TILES = (sb + 1023u) & ~1023u;
    const uint32_t STG = 65536;

    const int tid = threadIdx.x, wid = tid >> 5, lane = tid & 31;
    const int bm = blockIdx.y * 128, bn = blockIdx.x * 128;
    const int warp_m = wid & 1, warp_n = wid >> 1;
    const int nC = K >> 6;

    auto load_chunk = [&](int ci, int s) {
        const int k0 = ci << 6;
        const uint32_t stg = TILES + s * STG;
#pragma unroll
        for (int t = 0; t < 4; t++) {
            const int g = tid + t * 256;
            const int row = g >> 3;
            const int col8 = (g & 7) * 8;
            const uint32_t so = swz((uint32_t)(row * 128 + col8 * 2));
            const size_t ia = (size_t)(bm + row) * K + k0 + col8;
            const size_t ib = (size_t)(bn + row) * K + k0 + col8;
            cp16(stg + so,         Ah + ia);
            cp16(stg + 16384 + so, Al + ia);
            cp16(stg + 32768 + so, Wh + ib);
            cp16(stg + 49152 + so, Wl + ib);
        }
        CP_COMMIT();
    };

    const uint32_t mA = warp_m * 64 + ((lane >> 3) & 1) * 8 + (lane & 7);
    const uint32_t kA = (lane >> 4) * 8;
    const uint32_t nB = warp_n * 32 + (lane >> 4) * 8 + (lane & 7);
    const uint32_t kB = ((lane >> 3) & 1) * 8;

    float acc[4][4][4];
#pragma unroll
    for (int i = 0; i < 4; i++)
#pragma unroll
        for (int j = 0; j < 4; j++)
#pragma unroll
            for (int e = 0; e < 4; e++) acc[i][j][e] = 0.f;

    load_chunk(0, 0);
    if (nC > 1) load_chunk(1, 1);

    for (int i = 0; i < nC; i++) {
        const int s = i - (i / 3) * 3;
        if (i < nC - 1) { CP_WAIT(1); } else { CP_WAIT(0); }
        __syncthreads();
        if (i + 2 < nC) load_chunk(i + 2, (i + 2) - ((i + 2) / 3) * 3);

        const uint32_t stg = TILES + s * STG;
        const uint32_t Ahb = stg, Alb = stg + 16384;
        const uint32_t Bhb = stg + 32768, Blb = stg + 49152;

#pragma unroll
        for (int ks = 0; ks < 4; ks++) {
            const uint32_t oB0 = swz(nB * 128 + (ks * 16 + kB) * 2);
            const uint32_t oB1 = swz((nB + 16) * 128 + (ks * 16 + kB) * 2);
            uint32_t bh0[4], bh1[4], bl0[4], bl1[4];
            ldsm4(bh0, Bhb + oB0);
            ldsm4(bh1, Bhb + oB1);
            ldsm4(bl0, Blb + oB0);
            ldsm4(bl1, Blb + oB1);
#pragma unroll
            for (int mi = 0; mi < 4; mi++) {
                const uint32_t oA = swz((mA + mi * 16) * 128 + (ks * 16 + kA) * 2);
                uint32_t ah[4], al[4];
                ldsm4(ah, Ahb + oA);
                ldsm4(al, Alb + oA);
#pragma unroll
                for (int ni = 0; ni < 4; ni++) {
                    const uint32_t* bhp = (ni < 2) ? &bh0[(ni & 1) * 2] : &bh1[(ni & 1) * 2];
                    const uint32_t* blp = (ni < 2) ? &bl0[(ni & 1) * 2] : &bl1[(ni & 1) * 2];
                    mma_f16(acc[mi][ni], ah, bhp);
                    mma_f16(acc[mi][ni], ah, blp);
                    mma_f16(acc[mi][ni], al, bhp);
                }
            }
        }
        __syncthreads();
    }

    const int r0l   = lane >> 2;
    const int cpair = (lane & 3) * 2;
    const int mbase = bm + warp_m * 64;
    const int nbase = bn + warp_n * 32;
#pragma unroll
    for (int mi = 0; mi < 4; mi++) {
        const int row0 = mbase + mi * 16 + r0l;
        const int row1 = row0 + 8;
#pragma unroll
        for (int ni = 0; ni < 4; ni++) {
            const int col = nbase + ni * 8 + cpair;
            const float2 bv = *(const float2*)&bias[col];
            *(float2*)&Cf[(size_t)row0 * N + col] =
                make_float2(acc[mi][ni][0] + bv.x, acc[mi][ni][1] + bv.y);
            *(float2*)&Cf[(size_t)row1 * N + col] =
                make_float2(acc[mi][ni][2] + bv.x, acc[mi][ni][3] + bv.y);
        }
    }
}

// ---------------------------------------------------------------------------
DEVI float2 block_reduce2(float2 v, float2* sbuf) {
    const int lane = threadIdx.x & 31, wid = threadIdx.x >> 5;
#pragma unroll
    for (int o = 16; o > 0; o >>= 1) {
        v.x += __shfl_xor_sync(0xffffffffu, v.x, o);
        v.y += __shfl_xor_sync(0xffffffffu, v.y, o);
    }
    if (lane == 0) sbuf[wid] = v;
    __syncthreads();
    if (wid == 0) {
        float2 t = (lane < 8) ? sbuf[lane] : make_float2(0.f, 0.f);
#pragma unroll
        for (int o = 4; o > 0; o >>= 1) {
            t.x += __shfl_xor_sync(0xffffffffu, t.x, o);
            t.y += __shfl_xor_sync(0xffffffffu, t.y, o);
        }
        if (lane == 0) sbuf[0] = t;
    }
    __syncthreads();
    float2 r = sbuf[0];
    __syncthreads();
    return r;
}

// ---------------------------------------------------------------------------
// Layer-1: 8 rows/block, weights cached in smem; fp16 outputs
// ---------------------------------------------------------------------------
__global__ __launch_bounds__(256)
void layer1_k(const float* __restrict__ x,
              const float* __restrict__ aW1, const float* __restrict__ ab1,
              const float* __restrict__ ag1, const float* __restrict__ abe1,
              const float* __restrict__ pW1, const float* __restrict__ pb1,
              const float* __restrict__ pg1, const float* __restrict__ pbe1,
              __half* __restrict__ h1, __half* __restrict__ pq)
{
    extern __shared__ float sw[];
    float2* W  = (float2*)sw;
    float*  Bb = sw + 8192;
    float*  Gg = sw + 12288;
    float*  Be = sw + 16384;
    __shared__ float2 sbuf[8];

    const int tid = threadIdx.x;
    const int rb = blockIdx.x * 8;

    for (int i = tid; i < 4096; i += 256) {
        W[i]  = ((const float2*)aW1)[i];
        Bb[i] = ab1[i]; Gg[i] = ag1[i]; Be[i] = abe1[i];
    }
    __syncthreads();
    for (int r = 0; r < 8; r++) {
        const int b = rb + r;
        const float x0 = x[2 * b], x1 = x[2 * b + 1];
        float2 ss = make_float2(0.f, 0.f);
#pragma unroll
        for (int t = 0; t < 16; t++) {
            const int i = tid + t * 256;
            const float v = fmaf(W[i].y, x1, fmaf(W[i].x, x0, Bb[i]));
            ss.x += v; ss.y += v * v;
        }
        const float2 rr = block_reduce2(ss, sbuf);
        const float m = rr.x * (1.f / 4096.f);
        const float rstd = rsqrtf(rr.y * (1.f / 4096.f) - m * m + 1e-5f);
#pragma unroll
        for (int t = 0; t < 16; t++) {
            const int i = tid + t * 256;
            const float v = fmaf(W[i].y, x1, fmaf(W[i].x, x0, Bb[i]));
            const float hh = (v - m) * rstd * Gg[i] + Be[i];
            const float g = 0.5f * hh * (1.f + erff(hh * 0.70710678118654752f));
            h1[(size_t)b * 4096 + i] = __float2half_rn(g);
        }
    }
    __syncthreads();

    for (int i = tid; i < 2048; i += 256) {
        W[i]  = ((const float2*)pW1)[i];
        Bb[i] = pb1[i]; Gg[i] = pg1[i]; Be[i] = pbe1[i];
    }
    __syncthreads();
    for (int r = 0; r < 8; r++) {
        const int b = rb + r;
        const float x0 = x[2 * b], x1 = x[2 * b + 1];
        float2 ss = make_float2(0.f, 0.f);
#pragma unroll
        for (int t = 0; t < 8; t++) {
            const int i = tid + t * 256;
            const float v = fmaf(W[i].y, x1, fmaf(W[i].x, x0, Bb[i]));
            ss.x += v; ss.y += v * v;
        }
        const float2 rr = block_reduce2(ss, sbuf);
        const float m = rr.x * (1.f / 2048.f);
        const float rstd = rsqrtf(rr.y * (1.f / 2048.f) - m * m + 1e-5f);
#pragma unroll
        for (int t = 0; t < 8; t++) {
            const int i = tid + t * 256;
            const float v = fmaf(W[i].y, x1, fmaf(W[i].x, x0, Bb[i]));
            const float hh = (v - m) * rstd * Gg[i] + Be[i];
            // SiLU via MUFU exp (rel err ~1e-6)
            pq[(size_t)b * 2048 + i] = __float2half_rn(hh / (1.f + __expf(-hh)));
        }
    }
}

// ---------------------------------------------------------------------------
// LN + tanh over row of 2048, fp16 in (one uint4/thread) -> fp16 out
// ---------------------------------------------------------------------------
__global__ __launch_bounds__(256)
void ln_tanh_kernel(const __half* __restrict__ in,
                    const float* __restrict__ g, const float* __restrict__ be,
                    __half* __restrict__ oq)
{
    __shared__ float2 sbuf[8];
    const int b = blockIdx.x, tid = threadIdx.x;
    const uint4 raw = *(const uint4*)(in + (size_t)b * 2048 + tid * 8);
    float va[8];
    {
        const __half2* hp = (const __half2*)&raw;
#pragma unroll
        for (int j = 0; j < 4; j++) {
            const float2 f = __half22float2(hp[j]);
            va[2 * j] = f.x; va[2 * j + 1] = f.y;
        }
    }
    float2 ss = make_float2(0.f, 0.f);
#pragma unroll
    for (int j = 0; j < 8; j++) { ss.x += va[j]; ss.y += va[j] * va[j]; }
    const float2 r = block_reduce2(ss, sbuf);
    const float m = r.x * (1.f / 2048.f);
    const float rstd = rsqrtf(r.y * (1.f / 2048.f) - m * m + 1e-5f);

    const int i0 = tid * 8;
    const float4 g0 = *(const float4*)&g[i0];
    const float4 g1 = *(const float4*)&g[i0 + 4];
    const float4 e0 = *(const float4*)&be[i0];
    const float4 e1 = *(const float4*)&be[i0 + 4];
    const float gv[8] = {g0.x, g0.y, g0.z, g0.w, g1.x, g1.y, g1.z, g1.w};
    const float ev[8] = {e0.x, e0.y, e0.z, e0.w, e1.x, e1.y, e1.z, e1.w};
    uint4 outw;
    uint32_t* ow = (uint32_t*)&outw;
#pragma unroll
    for (int j = 0; j < 4; j++) {
        const float v0 = tanh_fast((va[2 * j]     - m) * rstd * gv[2 * j]     + ev[2 * j]);
        const float v1 = tanh_fast((va[2 * j + 1] - m) * rstd * gv[2 * j + 1] + ev[2 * j + 1]);
        ow[j] = pack2h(v0, v1);
    }
    *(uint4*)(oq + (size_t)b * 2048 + i0) = outw;
}

// ---------------------------------------------------------------------------
// rot table precompute: (f0,p0,f1,p1) + rz per q (1024 entries)
// ---------------------------------------------------------------------------
__global__ __launch_bounds__(256)
void rot_tab_kernel(const float* __restrict__ rf, const float* __restrict__ rp,
                    float4* __restrict__ tab, float* __restrict__ rz)
{
    const int q = blockIdx.x * 256 + threadIdx.x;   // 1024 total
    const float* f = rf + 4 * 1024 * 3 + 3 * q;
    const float* p = rp + 4 * 1024 * 3 + 3 * q;
    tab[q] = make_float4(f[0], p[0], f[1], p[1]);
    rz[q] = tanhf(p[2]);   // accurate (1024 evals only)
}

// ---------------------------------------------------------------------------
// qs mixing: fp16 amp/ph in (4/thread), table-driven, MUFU sin/cos
// ---------------------------------------------------------------------------
__global__ __launch_bounds__(256)
void qs_kernel(const __half* __restrict__ amp, const __half* __restrict__ phv,
               const float4* __restrict__ tab, const float* __restrict__ rz,
               __half* __restrict__ q)
{
    const int i4 = (blockIdx.x * 256 + threadIdx.x) * 4;
    const int q0 = i4 & 1023;
    const uint2 ar = *(const uint2*)(amp + i4);
    const uint2 pr = *(const uint2*)(phv + i4);
    const __half2* ah = (const __half2*)&ar;
    const __half2* ph = (const __half2*)&pr;
    const float2 a01 = __half22float2(ah[0]), a23 = __half22float2(ah[1]);
    const float2 p01 = __half22float2(ph[0]), p23 = __half22float2(ph[1]);
    const float av[4] = {a01.x, a01.y, a23.x, a23.y};
    const float pv[4] = {p01.x, p01.y, p23.x, p23.y};
    uint32_t ow[2];
    float qv[4];
#pragma unroll
    for (int j = 0; j < 4; j++) {
        const float4 t = tab[q0 + j];
        const float rx = sin_fast(fmaf(av[j], t.x, t.y));
        const float ry = cos_fast(fmaf(pv[j], t.z, t.w));
        qv[j] = (rx + ry + rz[q0 + j]) * (1.f / 3.f);
    }
    ow[0] = pack2h(qv[0], qv[1]);
    ow[1] = pack2h(qv[2], qv[3]);
    *(uint2*)(q + i4) = make_uint2(ow[0], ow[1]);
}

// ---------------------------------------------------------------------------
__global__ __launch_bounds__(256)
void wconv_kernel(const float* __restrict__ s, __half* __restrict__ h, int n)
{
    const int i = blockIdx.x * 256 + threadIdx.x;
    if (i < n) h[i] = __float2half_rn(s[i]);
}

__global__ __launch_bounds__(256)
void wsplit_kernel(const float* __restrict__ s,
                   __half* __restrict__ h, __half* __restrict__ l, int n)
{
    const int i = blockIdx.x * 256 + threadIdx.x;
    if (i < n) {
        __half hh, ll;
        split_h(s[i], hh, ll);
        h[i] = hh; l[i] = ll;
    }
}

__global__ void tsplit_kernel(const float* __restrict__ W,
                              __half* __restrict__ th, __half* __restrict__ tl)
{
    __shared__ float tile[32][33];
    const int tx = threadIdx.x, ty = threadIdx.y;
    const int bx = blockIdx.x * 32, by = blockIdx.y * 32;
#pragma unroll
    for (int r = 0; r < 4; r++)
        tile[ty * 4 + r][tx] = W[(size_t)(by + ty * 4 + r) * 1024 + bx + tx];
    __syncthreads();
#pragma unroll
    for (int r = 0; r < 4; r++) {
        const float v = tile[tx][ty * 4 + r];
        __half h, l; split_h(v, h, l);
        const size_t o = (size_t)(bx + ty * 4 + r) * 1024 + by + tx;
        th[o] = h; tl[o] = l;
    }
}

__global__ __launch_bounds__(256)
void bfuse_kernel(const float* __restrict__ Wout, const float* __restrict__ bv,
                  const float* __restrict__ bout, float* __restrict__ bf)
{
    __shared__ float2 sbuf[8];
    const int o = blockIdx.x, tid = threadIdx.x;
    float s = 0.f;
#pragma unroll
    for (int t = 0; t < 4; t++) {
        const int i = tid + t * 256;
        s = fmaf(Wout[(size_t)o * 1024 + i], bv[i], s);
    }
    const float2 r = block_reduce2(make_float2(s, 0.f), sbuf);
    if (tid == 0) bf[o] = r.x + bout[o];
}

// ---------------------------------------------------------------------------
extern "C" void kernel_launch(void* const* d_in, const int* in_sizes, int n_in,
                              void* d_out, int out_size)
{
    const float* x    = (const float*)d_in[0];
    const float* aW1  = (const float*)d_in[1];
    const float* ab1  = (const float*)d_in[2];
    const float* ag1  = (const float*)d_in[3];
    const float* abe1 = (const float*)d_in[4];
    const float* aW2  = (const float*)d_in[5];
    const float* ab2  = (const float*)d_in[6];
    const float* ag2  = (const float*)d_in[7];
    const float* abe2 = (const float*)d_in[8];
    const float* aW3  = (const float*)d_in[9];
    const float* ab3  = (const float*)d_in[10];
    const float* pW1  = (const float*)d_in[11];
    const float* pb1  = (const float*)d_in[12];
    const float* pg1  = (const float*)d_in[13];
    const float* pbe1 = (const float*)d_in[14];
    const float* pW2  = (const float*)d_in[15];
    const float* pb2  = (const float*)d_in[16];
    const float* rf   = (const float*)d_in[17];
    const float* rp   = (const float*)d_in[18];
    const float* winV = (const float*)d_in[19] + (size_t)2048 * 1024;
    const float* binV = (const float*)d_in[20] + 2048;
    const float* wout = (const float*)d_in[21];
    const float* bout = (const float*)d_in[22];
    float* out = (float*)d_out;

    __half *h1, *pq, *t2p, *t2q, *amph, *phh, *qs;
    __half *w2, *w3, *pw2, *wvth, *wvtl, *woh, *wol, *wf;
    float *wff, *bfused, *bzero, *rz;
    float4* rtab;
    cudaGetSymbolAddress((void**)&h1, g_h1);
    cudaGetSymbolAddress((void**)&pq, g_pq);
    cudaGetSymbolAddress((void**)&t2p, g_t2p);
    cudaGetSymbolAddress((void**)&t2q, g_t2q);
    cudaGetSymbolAddress((void**)&amph, g_amph);
    cudaGetSymbolAddress((void**)&phh, g_phh);
    cudaGetSymbolAddress((void**)&qs, g_qs);
    cudaGetSymbolAddress((void**)&w2, g_w2);
    cudaGetSymbolAddress((void**)&w3, g_w3);
    cudaGetSymbolAddress((void**)&pw2, g_pw2);
    cudaGetSymbolAddress((void**)&wvth, g_wvth); cudaGetSymbolAddress((void**)&wvtl, g_wvtl);
    cudaGetSymbolAddress((void**)&woh, g_woh); cudaGetSymbolAddress((void**)&wol, g_wol);
    cudaGetSymbolAddress((void**)&wff, g_wff);
    cudaGetSymbolAddress((void**)&wf, g_wf);
    cudaGetSymbolAddress((void**)&bfused, g_bfused);
    cudaGetSymbolAddress((void**)&bzero, g_bzero);
    cudaGetSymbolAddress((void**)&rtab, g_rtab);
    cudaGetSymbolAddress((void**)&rz, g_rz);

    const int SMEMB = 1024 + 4 * 49152;
    cudaFuncSetAttribute(gemm_f16<0>, cudaFuncAttributeMaxDynamicSharedMemorySize, SMEMB);
    cudaFuncSetAttribute(gemm_f16<2>, cudaFuncAttributeMaxDynamicSharedMemorySize, SMEMB);
    cudaFuncSetAttribute(gemm_f16<3>, cudaFuncAttributeMaxDynamicSharedMemorySize, SMEMB);
    const int SMEMP = 1024 + 3 * 65536;
    cudaFuncSetAttribute(gemm3_pre, cudaFuncAttributeMaxDynamicSharedMemorySize, SMEMP);
    const int L1SMEM = 81920;
    cudaFuncSetAttribute(layer1_k, cudaFuncAttributeMaxDynamicSharedMemorySize, L1SMEM);

    const int M = 16384;

    // W2 conversion first, then layer1
    wconv_kernel<<<(2048 * 4096) / 256, 256>>>(aW2, w2, 2048 * 4096);
    layer1_k<<<M / 8, 256, L1SMEM>>>(x, aW1, ab1, ag1, abe1, pW1, pb1, pg1, pbe1,
                                     h1, pq);
    wconv_kernel<<<(1024 * 2048) / 256, 256>>>(aW3, w3, 1024 * 2048);

    // GEMM1: t2pre = h1 @ W2^T + b2  (fp16 out)
    gemm_f16<2><<<dim3(16, 64), 256, SMEMB>>>(h1, w2, ab2, nullptr, t2p,
                                              nullptr, nullptr, nullptr, nullptr,
                                              2048, 4096);

    // Fused-weight precompute + rot table (independent small work)
    wconv_kernel<<<(1024 * 2048) / 256, 256>>>(pW2, pw2, 1024 * 2048);
    tsplit_kernel<<<dim3(32, 32), dim3(32, 8)>>>(winV, wvth, wvtl);
    wsplit_kernel<<<(1024 * 1024) / 256, 256>>>(wout, woh, wol, 1024 * 1024);
    gemm3_pre<<<dim3(8, 8), 256, SMEMP>>>(woh, wol, wvth, wvtl, bzero, wff,
                                          1024, 1024);
    bfuse_kernel<<<1024, 256>>>(wout, binV, bout, bfused);
    wconv_kernel<<<(1024 * 1024) / 256, 256>>>(wff, wf, 1024 * 1024);
    rot_tab_kernel<<<4, 256>>>(rf, rp, rtab, rz);

    ln_tanh_kernel<<<M, 256>>>(t2p, ag2, abe2, t2q);

    // merged GEMM2 (amp) + GEMM3 (phase, tanh), fp16 outputs
    gemm_f16<3><<<dim3(8, 64, 2), 256, SMEMB>>>(t2q, w3, ab3, nullptr, amph,
                                                pq, pw2, pb2, phh,
                                                1024, 2048);

    qs_kernel<<<(M * 1024) / 1024, 256>>>(amph, phh, rtab, rz, qs);

    // out = qs @ Wfused^T + bfused
    gemm_f16<0><<<dim3(8, 64), 256, SMEMB>>>(qs, wf, bfused, out, nullptr,
                                             nullptr, nullptr, nullptr, nullptr,
                                             1024, 1024);
}

// round 17
// speedup vs baseline: 1.1840x; 1.0203x over previous
#include <cuda_runtime.h>
#include <cuda_fp16.h>
#include <cstdint>

// ===========================================================================
// B=16384, Q=1024, F=2. mma.sync m16n8k16 fp16 single-plane (1 MMA term).
// Main GEMM: CTA 256x128, warp 64x64, K-chunk 128 (two 64-col sub-chunks),
// 2-stage ring (96KB/stage) -> HALF the barriers of the K=64 version.
// GEMM2+GEMM3 merged via gridDim.z; GEMM4+GEMM5 fused algebraically.
// Elementwise tail uses MUFU approximations.
// ===========================================================================

#define DEVI __device__ __forceinline__

DEVI uint32_t smem_u32(const void* p) {
    uint32_t r;
    asm("{ .reg .u64 t; cvta.to.shared.u64 t, %1; cvt.u32.u64 %0, t; }"
        : "=r"(r) : "l"(p));
    return r;
}
DEVI uint32_t swz(uint32_t x) { return x ^ ((x >> 3) & 0x70); }

DEVI void cp16(uint32_t dst, const void* src) {
    asm volatile("cp.async.cg.shared.global [%0], [%1], 16;"
                 :: "r"(dst), "l"(src));
}
#define CP_COMMIT() asm volatile("cp.async.commit_group;" ::: "memory")
#define CP_WAIT(n)  asm volatile("cp.async.wait_group %0;" :: "n"(n) : "memory")

DEVI void ldsm4(uint32_t* r, uint32_t a) {
    asm volatile("ldmatrix.sync.aligned.m8n8.x4.shared.b16 {%0,%1,%2,%3}, [%4];"
                 : "=r"(r[0]), "=r"(r[1]), "=r"(r[2]), "=r"(r[3]) : "r"(a));
}
DEVI void mma_f16(float* d, const uint32_t* a, const uint32_t* b) {
    asm volatile("mma.sync.aligned.m16n8k16.row.col.f32.f16.f16.f32 "
                 "{%0,%1,%2,%3},{%4,%5,%6,%7},{%8,%9},{%0,%1,%2,%3};"
                 : "+f"(d[0]), "+f"(d[1]), "+f"(d[2]), "+f"(d[3])
                 : "r"(a[0]), "r"(a[1]), "r"(a[2]), "r"(a[3]),
                   "r"(b[0]), "r"(b[1]));
}

DEVI float tanh_fast(float x) {
    float y;
    asm("tanh.approx.f32 %0, %1;" : "=f"(y) : "f"(x));
    return y;
}
DEVI float sin_fast(float x) {
    float y;
    asm("sin.approx.f32 %0, %1;" : "=f"(y) : "f"(x));
    return y;
}
DEVI float cos_fast(float x) {
    float y;
    asm("cos.approx.f32 %0, %1;" : "=f"(y) : "f"(x));
    return y;
}

DEVI void split_h(float v, __half& h, __half& l) {
    h = __float2half_rn(v);
    l = __float2half_rn(v - __half2float(h));
}
DEVI uint32_t pack2h(float a, float b) {
    __half2 p = __floats2half2_rn(a, b);
    return *(uint32_t*)&p;
}

// ---------------------------------------------------------------------------
// Scratch
// ---------------------------------------------------------------------------
__device__ __half g_h1  [(size_t)16384 * 4096];
__device__ __half g_pq  [(size_t)16384 * 2048];
__device__ __half g_t2p [(size_t)16384 * 2048];
__device__ __half g_t2q [(size_t)16384 * 2048];
__device__ __half g_amph[(size_t)16384 * 1024];
__device__ __half g_phh [(size_t)16384 * 1024];
__device__ __half g_qs  [(size_t)16384 * 1024];
__device__ __half g_w2  [(size_t)2048 * 4096];
__device__ __half g_w3  [(size_t)1024 * 2048];
__device__ __half g_pw2 [(size_t)1024 * 2048];
__device__ __half g_wvth[(size_t)1024 * 1024], g_wvtl[(size_t)1024 * 1024];
__device__ __half g_woh [(size_t)1024 * 1024], g_wol [(size_t)1024 * 1024];
__device__ float  g_wff [(size_t)1024 * 1024];
__device__ __half g_wf  [(size_t)1024 * 1024];
__device__ float  g_bfused[1024];
__device__ float  g_bzero[1024];
__device__ float4 g_rtab[1024];
__device__ float  g_rz  [1024];

// ---------------------------------------------------------------------------
// Main GEMM (1-term): C[m,n] = sum_k A[m,k]*W[n,k] + bias[n]
// CTA 256x128, 8 warps 4(m)x2(n), warp tile 64x64.
// K-chunk 128 stored as two 64-col sub-chunks:
//   stage layout: A0(32KB) | A1(32KB) | W0(16KB) | W1(16KB) = 96KB
// 2-stage ring: preload chunk 0; per iter: CP_WAIT(0), sync, refill i+1
// into buffer 1-s (consumed at iter i-1 -> safe), MMA both sub-chunks.
// EPI: 0 = fp32 store; 2 = fp16 store;
//      3 = merged two-GEMM, fp16 store (z==1 -> second set + tanh)
// ---------------------------------------------------------------------------
template<int EPI>
__global__ __launch_bounds__(256, 1)
void gemm_f16(const __half* __restrict__ A, const __half* __restrict__ W,
              const float* __restrict__ bias, float* __restrict__ Cf,
              __half* __restrict__ Chf,
              const __half* A2, const __half* W2p,
              const float* bias2, __half* Chf2,
              int N, int K)
{
    extern __shared__ char smem[];
    const uint32_t sb = smem_u32(smem);
    const uint32_t TILES = (sb + 1023u) & ~1023u;
    const uint32_t STG = 98304;   // A 64KB | W 32KB

    bool second = false;
    if (EPI == 3 && blockIdx.z == 1) {
        second = true;
        A = A2; W = W2p; bias = bias2; Chf = Chf2;
    }

    const int tid = threadIdx.x, wid = tid >> 5, lane = tid & 31;
    const int bm = blockIdx.y * 256, bn = blockIdx.x * 128;
    const int warp_m = wid & 3, warp_n = wid >> 2;
    const int nC = K >> 7;   // 128-wide chunks

    auto load_chunk = [&](int ci, int s) {
        const uint32_t stg = TILES + s * STG;
#pragma unroll
        for (int kh = 0; kh < 2; kh++) {
            const int k0 = (ci << 7) + kh * 64;
            const uint32_t ab = stg + kh * 32768;
            const uint32_t wb = stg + 65536 + kh * 16384;
#pragma unroll
            for (int t = 0; t < 8; t++) {          // A: 256 rows x 64 cols
                const int g = tid + t * 256;
                const int row = g >> 3;
                const int col8 = (g & 7) * 8;
                const uint32_t so = swz((uint32_t)(row * 128 + col8 * 2));
                cp16(ab + so, A + (size_t)(bm + row) * K + k0 + col8);
            }
#pragma unroll
            for (int t = 0; t < 4; t++) {          // W: 128 rows x 64 cols
                const int g = tid + t * 256;
                const int row = g >> 3;
                const int col8 = (g & 7) * 8;
                const uint32_t so = swz((uint32_t)(row * 128 + col8 * 2));
                cp16(wb + so, W + (size_t)(bn + row) * K + k0 + col8);
            }
        }
        CP_COMMIT();
    };

    const uint32_t mA = warp_m * 64 + ((lane >> 3) & 1) * 8 + (lane & 7);
    const uint32_t kA = (lane >> 4) * 8;
    const uint32_t nB = warp_n * 64 + (lane >> 4) * 8 + (lane & 7);
    const uint32_t kB = ((lane >> 3) & 1) * 8;

    float acc[4][8][4];
#pragma unroll
    for (int i = 0; i < 4; i++)
#pragma unroll
        for (int j = 0; j < 8; j++)
#pragma unroll
            for (int e = 0; e < 4; e++) acc[i][j][e] = 0.f;

    load_chunk(0, 0);

    for (int i = 0; i < nC; i++) {
        const int s = i & 1;
        CP_WAIT(0);          // chunk i resident
        __syncthreads();     // all warps past buffer 1-s (consumed at i-1)
        if (i + 1 < nC) load_chunk(i + 1, 1 - s);

        const uint32_t stg = TILES + s * STG;
#pragma unroll
        for (int kh = 0; kh < 2; kh++) {
            const uint32_t Ab = stg + kh * 32768;
            const uint32_t Bb = stg + 65536 + kh * 16384;
#pragma unroll
            for (int ks = 0; ks < 4; ks++) {
                uint32_t bh[4][4];
#pragma unroll
                for (int g = 0; g < 4; g++) {
                    const uint32_t oB = swz((nB + g * 16) * 128 + (ks * 16 + kB) * 2);
                    ldsm4(bh[g], Bb + oB);
                }
#pragma unroll
                for (int mi = 0; mi < 4; mi++) {
                    const uint32_t oA = swz((mA + mi * 16) * 128 + (ks * 16 + kA) * 2);
                    uint32_t ah[4];
                    ldsm4(ah, Ab + oA);
#pragma unroll
                    for (int ni = 0; ni < 8; ni++)
                        mma_f16(acc[mi][ni], ah, &bh[ni >> 1][(ni & 1) * 2]);
                }
            }
        }
    }

    const int r0l   = lane >> 2;
    const int cpair = (lane & 3) * 2;
    const int mbase = bm + warp_m * 64;
    const int nbase = bn + warp_n * 64;

#pragma unroll
    for (int mi = 0; mi < 4; mi++) {
        const int row0 = mbase + mi * 16 + r0l;
        const int row1 = row0 + 8;
#pragma unroll
        for (int ni = 0; ni < 8; ni++) {
            const int col = nbase + ni * 8 + cpair;
            const float2 bv = *(const float2*)&bias[col];
            float v0 = acc[mi][ni][0] + bv.x;
            float v1 = acc[mi][ni][1] + bv.y;
            float v2 = acc[mi][ni][2] + bv.x;
            float v3 = acc[mi][ni][3] + bv.y;
            if (EPI == 3 && second) {
                v0 = tanh_fast(v0); v1 = tanh_fast(v1);
                v2 = tanh_fast(v2); v3 = tanh_fast(v3);
            }
            if (EPI == 0) {
                *(float2*)&Cf[(size_t)row0 * N + col] = make_float2(v0, v1);
                *(float2*)&Cf[(size_t)row1 * N + col] = make_float2(v2, v3);
            } else {
                *(uint32_t*)&Chf[(size_t)row0 * N + col] = pack2h(v0, v1);
                *(uint32_t*)&Chf[(size_t)row1 * N + col] = pack2h(v2, v3);
            }
        }
    }
}

// ---------------------------------------------------------------------------
// Precompute GEMM (3-term, 2-plane both operands): Wfused = Wout @ Wv^T
// CTA 128x128, warp 64x32, 3-stage ring (safe refill i+2). K-chunk 64.
// ---------------------------------------------------------------------------
__global__ __launch_bounds__(256, 1)
void gemm3_pre(const __half* __restrict__ Ah, const __half* __restrict__ Al,
               const __half* __restrict__ Wh, const __half* __restrict__ Wl,
               const float* __restrict__ bias, float* __restrict__ Cf,
               int N, int K)
{
    extern __shared__ char smem[];
    const uint32_t sb = smem_u32(smem);
    const uint32_t TILES = (sb + 1023u) & ~1023u;
    const uint32_t STG = 65536;

    const int tid = threadIdx.x, wid = tid >> 5, lane = tid & 31;
    const int bm = blockIdx.y * 128, bn = blockIdx.x * 128;
    const int warp_m = wid & 1, warp_n = wid >> 1;
    const int nC = K >> 6;

    auto load_chunk = [&](int ci, int s) {
        const int k0 = ci << 6;
        const uint32_t stg = TILES + s * STG;
#pragma unroll
        for (int t = 0; t < 4; t++) {
            const int g = tid + t * 256;
            const int row = g >> 3;
            const int col8 = (g & 7) * 8;
            const uint32_t so = swz((uint32_t)(row * 128 + col8 * 2));
            const size_t ia = (size_t)(bm + row) * K + k0 + col8;
            const size_t ib = (size_t)(bn + row) * K + k0 + col8;
            cp16(stg + so,         Ah + ia);
            cp16(stg + 16384 + so, Al + ia);
            cp16(stg + 32768 + so, Wh + ib);
            cp16(stg + 49152 + so, Wl + ib);
        }
        CP_COMMIT();
    };

    const uint32_t mA = warp_m * 64 + ((lane >> 3) & 1) * 8 + (lane & 7);
    const uint32_t kA = (lane >> 4) * 8;
    const uint32_t nB = warp_n * 32 + (lane >> 4) * 8 + (lane & 7);
    const uint32_t kB = ((lane >> 3) & 1) * 8;

    float acc[4][4][4];
#pragma unroll
    for (int i = 0; i < 4; i++)
#pragma unroll
        for (int j = 0; j < 4; j++)
#pragma unroll
            for (int e = 0; e < 4; e++) acc[i][j][e] = 0.f;

    load_chunk(0, 0);
    if (nC > 1) load_chunk(1, 1);

    for (int i = 0; i < nC; i++) {
        const int s = i - (i / 3) * 3;
        if (i < nC - 1) { CP_WAIT(1); } else { CP_WAIT(0); }
        __syncthreads();
        if (i + 2 < nC) load_chunk(i + 2, (i + 2) - ((i + 2) / 3) * 3);

        const uint32_t stg = TILES + s * STG;
        const uint32_t Ahb = stg, Alb = stg + 16384;
        const uint32_t Bhb = stg + 32768, Blb = stg + 49152;

#pragma unroll
        for (int ks = 0; ks < 4; ks++) {
            const uint32_t oB0 = swz(nB * 128 + (ks * 16 + kB) * 2);
            const uint32_t oB1 = swz((nB + 16) * 128 + (ks * 16 + kB) * 2);
            uint32_t bh0[4], bh1[4], bl0[4], bl1[4];
            ldsm4(bh0, Bhb + oB0);
            ldsm4(bh1, Bhb + oB1);
            ldsm4(bl0, Blb + oB0);
            ldsm4(bl1, Blb + oB1);
#pragma unroll
            for (int mi = 0; mi < 4; mi++) {
                const uint32_t oA = swz((mA + mi * 16) * 128 + (ks * 16 + kA) * 2);
                uint32_t ah[4], al[4];
                ldsm4(ah, Ahb + oA);
                ldsm4(al, Alb + oA);
#pragma unroll
                for (int ni = 0; ni < 4; ni++) {
                    const uint32_t* bhp = (ni < 2) ? &bh0[(ni & 1) * 2] : &bh1[(ni & 1) * 2];
                    const uint32_t* blp = (ni < 2) ? &bl0[(ni & 1) * 2] : &bl1[(ni & 1) * 2];
                    mma_f16(acc[mi][ni], ah, bhp);
                    mma_f16(acc[mi][ni], ah, blp);
                    mma_f16(acc[mi][ni], al, bhp);
                }
            }
        }
        __syncthreads();
    }

    const int r0l   = lane >> 2;
    const int cpair = (lane & 3) * 2;
    const int mbase = bm + warp_m * 64;
    const int nbase = bn + warp_n * 32;
#pragma unroll
    for (int mi = 0; mi < 4; mi++) {
        const int row0 = mbase + mi * 16 + r0l;
        const int row1 = row0 + 8;
#pragma unroll
        for (int ni = 0; ni < 4; ni++) {
            const int col = nbase + ni * 8 + cpair;
            const float2 bv = *(const float2*)&bias[col];
            *(float2*)&Cf[(size_t)row0 * N + col] =
                make_float2(acc[mi][ni][0] + bv.x, acc[mi][ni][1] + bv.y);
            *(float2*)&Cf[(size_t)row1 * N + col] =
                make_float2(acc[mi][ni][2] + bv.x, acc[mi][ni][3] + bv.y);
        }
    }
}

// ---------------------------------------------------------------------------
DEVI float2 block_reduce2(float2 v, float2* sbuf) {
    const int lane = threadIdx.x & 31, wid = threadIdx.x >> 5;
#pragma unroll
    for (int o = 16; o > 0; o >>= 1) {
        v.x += __shfl_xor_sync(0xffffffffu, v.x, o);
        v.y += __shfl_xor_sync(0xffffffffu, v.y, o);
    }
    if (lane == 0) sbuf[wid] = v;
    __syncthreads();
    if (wid == 0) {
        float2 t = (lane < 8) ? sbuf[lane] : make_float2(0.f, 0.f);
#pragma unroll
        for (int o = 4; o > 0; o >>= 1) {
            t.x += __shfl_xor_sync(0xffffffffu, t.x, o);
            t.y += __shfl_xor_sync(0xffffffffu, t.y, o);
        }
        if (lane == 0) sbuf[0] = t;
    }
    __syncthreads();
    float2 r = sbuf[0];
    __syncthreads();
    return r;
}

// ---------------------------------------------------------------------------
// Layer-1: 8 rows/block, weights cached in smem; fp16 outputs
// ---------------------------------------------------------------------------
__global__ __launch_bounds__(256)
void layer1_k(const float* __restrict__ x,
              const float* __restrict__ aW1, const float* __restrict__ ab1,
              const float* __restrict__ ag1, const float* __restrict__ abe1,
              const float* __restrict__ pW1, const float* __restrict__ pb1,
              const float* __restrict__ pg1, const float* __restrict__ pbe1,
              __half* __restrict__ h1, __half* __restrict__ pq)
{
    extern __shared__ float sw[];
    float2* W  = (float2*)sw;
    float*  Bb = sw + 8192;
    float*  Gg = sw + 12288;
    float*  Be = sw + 16384;
    __shared__ float2 sbuf[8];

    const int tid = threadIdx.x;
    const int rb = blockIdx.x * 8;

    for (int i = tid; i < 4096; i += 256) {
        W[i]  = ((const float2*)aW1)[i];
        Bb[i] = ab1[i]; Gg[i] = ag1[i]; Be[i] = abe1[i];
    }
    __syncthreads();
    for (int r = 0; r < 8; r++) {
        const int b = rb + r;
        const float x0 = x[2 * b], x1 = x[2 * b + 1];
        float2 ss = make_float2(0.f, 0.f);
#pragma unroll
        for (int t = 0; t < 16; t++) {
            const int i = tid + t * 256;
            const float v = fmaf(W[i].y, x1, fmaf(W[i].x, x0, Bb[i]));
            ss.x += v; ss.y += v * v;
        }
        const float2 rr = block_reduce2(ss, sbuf);
        const float m = rr.x * (1.f / 4096.f);
        const float rstd = rsqrtf(rr.y * (1.f / 4096.f) - m * m + 1e-5f);
#pragma unroll
        for (int t = 0; t < 16; t++) {
            const int i = tid + t * 256;
            const float v = fmaf(W[i].y, x1, fmaf(W[i].x, x0, Bb[i]));
            const float hh = (v - m) * rstd * Gg[i] + Be[i];
            const float g = 0.5f * hh * (1.f + erff(hh * 0.70710678118654752f));
            h1[(size_t)b * 4096 + i] = __float2half_rn(g);
        }
    }
    __syncthreads();

    for (int i = tid; i < 2048; i += 256) {
        W[i]  = ((const float2*)pW1)[i];
        Bb[i] = pb1[i]; Gg[i] = pg1[i]; Be[i] = pbe1[i];
    }
    __syncthreads();
    for (int r = 0; r < 8; r++) {
        const int b = rb + r;
        const float x0 = x[2 * b], x1 = x[2 * b + 1];
        float2 ss = make_float2(0.f, 0.f);
#pragma unroll
        for (int t = 0; t < 8; t++) {
            const int i = tid + t * 256;
            const float v = fmaf(W[i].y, x1, fmaf(W[i].x, x0, Bb[i]));
            ss.x += v; ss.y += v * v;
        }
        const float2 rr = block_reduce2(ss, sbuf);
        const float m = rr.x * (1.f / 2048.f);
        const float rstd = rsqrtf(rr.y * (1.f / 2048.f) - m * m + 1e-5f);
#pragma unroll
        for (int t = 0; t < 8; t++) {
            const int i = tid + t * 256;
            const float v = fmaf(W[i].y, x1, fmaf(W[i].x, x0, Bb[i]));
            const float hh = (v - m) * rstd * Gg[i] + Be[i];
            pq[(size_t)b * 2048 + i] = __float2half_rn(hh / (1.f + __expf(-hh)));
        }
    }
}

// ---------------------------------------------------------------------------
// LN + tanh over row of 2048, fp16 in (one uint4/thread) -> fp16 out
// ---------------------------------------------------------------------------
__global__ __launch_bounds__(256)
void ln_tanh_kernel(const __half* __restrict__ in,
                    const float* __restrict__ g, const float* __restrict__ be,
                    __half* __restrict__ oq)
{
    __shared__ float2 sbuf[8];
    const int b = blockIdx.x, tid = threadIdx.x;
    const uint4 raw = *(const uint4*)(in + (size_t)b * 2048 + tid * 8);
    float va[8];
    {
        const __half2* hp = (const __half2*)&raw;
#pragma unroll
        for (int j = 0; j < 4; j++) {
            const float2 f = __half22float2(hp[j]);
            va[2 * j] = f.x; va[2 * j + 1] = f.y;
        }
    }
    float2 ss = make_float2(0.f, 0.f);
#pragma unroll
    for (int j = 0; j < 8; j++) { ss.x += va[j]; ss.y += va[j] * va[j]; }
    const float2 r = block_reduce2(ss, sbuf);
    const float m = r.x * (1.f / 2048.f);
    const float rstd = rsqrtf(r.y * (1.f / 2048.f) - m * m + 1e-5f);

    const int i0 = tid * 8;
    const float4 g0 = *(const float4*)&g[i0];
    const float4 g1 = *(const float4*)&g[i0 + 4];
    const float4 e0 = *(const float4*)&be[i0];
    const float4 e1 = *(const float4*)&be[i0 + 4];
    const float gv[8] = {g0.x, g0.y, g0.z, g0.w, g1.x, g1.y, g1.z, g1.w};
    const float ev[8] = {e0.x, e0.y, e0.z, e0.w, e1.x, e1.y, e1.z, e1.w};
    uint4 outw;
    uint32_t* ow = (uint32_t*)&outw;
#pragma unroll
    for (int j = 0; j < 4; j++) {
        const float v0 = tanh_fast((va[2 * j]     - m) * rstd * gv[2 * j]     + ev[2 * j]);
        const float v1 = tanh_fast((va[2 * j + 1] - m) * rstd * gv[2 * j + 1] + ev[2 * j + 1]);
        ow[j] = pack2h(v0, v1);
    }
    *(uint4*)(oq + (size_t)b * 2048 + i0) = outw;
}

// ---------------------------------------------------------------------------
// rot table precompute: (f0,p0,f1,p1) + rz per q (1024 entries)
// ---------------------------------------------------------------------------
__global__ __launch_bounds__(256)
void rot_tab_kernel(const float* __restrict__ rf, const float* __restrict__ rp,
                    float4* __restrict__ tab, float* __restrict__ rz)
{
    const int q = blockIdx.x * 256 + threadIdx.x;
    const float* f = rf + 4 * 1024 * 3 + 3 * q;
    const float* p = rp + 4 * 1024 * 3 + 3 * q;
    tab[q] = make_float4(f[0], p[0], f[1], p[1]);
    rz[q] = tanhf(p[2]);
}

// ---------------------------------------------------------------------------
// qs mixing: fp16 amp/ph in (4/thread), table-driven, MUFU sin/cos
// ---------------------------------------------------------------------------
__global__ __launch_bounds__(256)
void qs_kernel(const __half* __restrict__ amp, const __half* __restrict__ phv,
               const float4* __restrict__ tab, const float* __restrict__ rz,
               __half* __restrict__ q)
{
    const int i4 = (blockIdx.x * 256 + threadIdx.x) * 4;
    const int q0 = i4 & 1023;
    const uint2 ar = *(const uint2*)(amp + i4);
    const uint2 pr = *(const uint2*)(phv + i4);
    const __half2* ah = (const __half2*)&ar;
    const __half2* ph = (const __half2*)&pr;
    const float2 a01 = __half22float2(ah[0]), a23 = __half22float2(ah[1]);
    const float2 p01 = __half22float2(ph[0]), p23 = __half22float2(ph[1]);
    const float av[4] = {a01.x, a01.y, a23.x, a23.y};
    const float pv[4] = {p01.x, p01.y, p23.x, p23.y};
    uint32_t ow[2];
    float qv[4];
#pragma unroll
    for (int j = 0; j < 4; j++) {
        const float4 t = tab[q0 + j];
        const float rx = sin_fast(fmaf(av[j], t.x, t.y));
        const float ry = cos_fast(fmaf(pv[j], t.z, t.w));
        qv[j] = (rx + ry + rz[q0 + j]) * (1.f / 3.f);
    }
    ow[0] = pack2h(qv[0], qv[1]);
    ow[1] = pack2h(qv[2], qv[3]);
    *(uint2*)(q + i4) = make_uint2(ow[0], ow[1]);
}

// ---------------------------------------------------------------------------
__global__ __launch_bounds__(256)
void wconv_kernel(const float* __restrict__ s, __half* __restrict__ h, int n)
{
    const int i = blockIdx.x * 256 + threadIdx.x;
    if (i < n) h[i] = __float2half_rn(s[i]);
}

__global__ __launch_bounds__(256)
void wsplit_kernel(const float* __restrict__ s,
                   __half* __restrict__ h, __half* __restrict__ l, int n)
{
    const int i = blockIdx.x * 256 + threadIdx.x;
    if (i < n) {
        __half hh, ll;
        split_h(s[i], hh, ll);
        h[i] = hh; l[i] = ll;
    }
}

__global__ void tsplit_kernel(const float* __restrict__ W,
                              __half* __restrict__ th, __half* __restrict__ tl)
{
    __shared__ float tile[32][33];
    const int tx = threadIdx.x, ty = threadIdx.y;
    const int bx = blockIdx.x * 32, by = blockIdx.y * 32;
#pragma unroll
    for (int r = 0; r < 4; r++)
        tile[ty * 4 + r][tx] = W[(size_t)(by + ty * 4 + r) * 1024 + bx + tx];
    __syncthreads();
#pragma unroll
    for (int r = 0; r < 4; r++) {
        const float v = tile[tx][ty * 4 + r];
        __half h, l; split_h(v, h, l);
        const size_t o = (size_t)(bx + ty * 4 + r) * 1024 + by + tx;
        th[o] = h; tl[o] = l;
    }
}

__global__ __launch_bounds__(256)
void bfuse_kernel(const float* __restrict__ Wout, const float* __restrict__ bv,
                  const float* __restrict__ bout, float* __restrict__ bf)
{
    __shared__ float2 sbuf[8];
    const int o = blockIdx.x, tid = threadIdx.x;
    float s = 0.f;
#pragma unroll
    for (int t = 0; t < 4; t++) {
        const int i = tid + t * 256;
        s = fmaf(Wout[(size_t)o * 1024 + i], bv[i], s);
    }
    const float2 r = block_reduce2(make_float2(s, 0.f), sbuf);
    if (tid == 0) bf[o] = r.x + bout[o];
}

// ---------------------------------------------------------------------------
extern "C" void kernel_launch(void* const* d_in, const int* in_sizes, int n_in,
                              void* d_out, int out_size)
{
    const float* x    = (const float*)d_in[0];
    const float* aW1  = (const float*)d_in[1];
    const float* ab1  = (const float*)d_in[2];
    const float* ag1  = (const float*)d_in[3];
    const float* abe1 = (const float*)d_in[4];
    const float* aW2  = (const float*)d_in[5];
    const float* ab2  = (const float*)d_in[6];
    const float* ag2  = (const float*)d_in[7];
    const float* abe2 = (const float*)d_in[8];
    const float* aW3  = (const float*)d_in[9];
    const float* ab3  = (const float*)d_in[10];
    const float* pW1  = (const float*)d_in[11];
    const float* pb1  = (const float*)d_in[12];
    const float* pg1  = (const float*)d_in[13];
    const float* pbe1 = (const float*)d_in[14];
    const float* pW2  = (const float*)d_in[15];
    const float* pb2  = (const float*)d_in[16];
    const float* rf   = (const float*)d_in[17];
    const float* rp   = (const float*)d_in[18];
    const float* winV = (const float*)d_in[19] + (size_t)2048 * 1024;
    const float* binV = (const float*)d_in[20] + 2048;
    const float* wout = (const float*)d_in[21];
    const float* bout = (const float*)d_in[22];
    float* out = (float*)d_out;

    __half *h1, *pq, *t2p, *t2q, *amph, *phh, *qs;
    __half *w2, *w3, *pw2, *wvth, *wvtl, *woh, *wol, *wf;
    float *wff, *bfused, *bzero, *rz;
    float4* rtab;
    cudaGetSymbolAddress((void**)&h1, g_h1);
    cudaGetSymbolAddress((void**)&pq, g_pq);
    cudaGetSymbolAddress((void**)&t2p, g_t2p);
    cudaGetSymbolAddress((void**)&t2q, g_t2q);
    cudaGetSymbolAddress((void**)&amph, g_amph);
    cudaGetSymbolAddress((void**)&phh, g_phh);
    cudaGetSymbolAddress((void**)&qs, g_qs);
    cudaGetSymbolAddress((void**)&w2, g_w2);
    cudaGetSymbolAddress((void**)&w3, g_w3);
    cudaGetSymbolAddress((void**)&pw2, g_pw2);
    cudaGetSymbolAddress((void**)&wvth, g_wvth); cudaGetSymbolAddress((void**)&wvtl, g_wvtl);
    cudaGetSymbolAddress((void**)&woh, g_woh); cudaGetSymbolAddress((void**)&wol, g_wol);
    cudaGetSymbolAddress((void**)&wff, g_wff);
    cudaGetSymbolAddress((void**)&wf, g_wf);
    cudaGetSymbolAddress((void**)&bfused, g_bfused);
    cudaGetSymbolAddress((void**)&bzero, g_bzero);
    cudaGetSymbolAddress((void**)&rtab, g_rtab);
    cudaGetSymbolAddress((void**)&rz, g_rz);

    const int SMEMB = 1024 + 2 * 98304;   // 197,632 B
    cudaFuncSetAttribute(gemm_f16<0>, cudaFuncAttributeMaxDynamicSharedMemorySize, SMEMB);
    cudaFuncSetAttribute(gemm_f16<2>, cudaFuncAttributeMaxDynamicSharedMemorySize, SMEMB);
    cudaFuncSetAttribute(gemm_f16<3>, cudaFuncAttributeMaxDynamicSharedMemorySize, SMEMB);
    const int SMEMP = 1024 + 3 * 65536;
    cudaFuncSetAttribute(gemm3_pre, cudaFuncAttributeMaxDynamicSharedMemorySize, SMEMP);
    const int L1SMEM = 81920;
    cudaFuncSetAttribute(layer1_k, cudaFuncAttributeMaxDynamicSharedMemorySize, L1SMEM);

    const int M = 16384;

    // W2 conversion first, then layer1
    wconv_kernel<<<(2048 * 4096) / 256, 256>>>(aW2, w2, 2048 * 4096);
    layer1_k<<<M / 8, 256, L1SMEM>>>(x, aW1, ab1, ag1, abe1, pW1, pb1, pg1, pbe1,
                                     h1, pq);
    wconv_kernel<<<(1024 * 2048) / 256, 256>>>(aW3, w3, 1024 * 2048);

    // GEMM1: t2pre = h1 @ W2^T + b2  (fp16 out)
    gemm_f16<2><<<dim3(16, 64), 256, SMEMB>>>(h1, w2, ab2, nullptr, t2p,
                                              nullptr, nullptr, nullptr, nullptr,
                                              2048, 4096);

    // Fused-weight precompute + rot table
    wconv_kernel<<<(1024 * 2048) / 256, 256>>>(pW2, pw2, 1024 * 2048);
    tsplit_kernel<<<dim3(32, 32), dim3(32, 8)>>>(winV, wvth, wvtl);
    wsplit_kernel<<<(1024 * 1024) / 256, 256>>>(wout, woh, wol, 1024 * 1024);
    gemm3_pre<<<dim3(8, 8), 256, SMEMP>>>(woh, wol, wvth, wvtl, bzero, wff,
                                          1024, 1024);
    bfuse_kernel<<<1024, 256>>>(wout, binV, bout, bfused);
    wconv_kernel<<<(1024 * 1024) / 256, 256>>>(wff, wf, 1024 * 1024);
    rot_tab_kernel<<<4, 256>>>(rf, rp, rtab, rz);

    ln_tanh_kernel<<<M, 256>>>(t2p, ag2, abe2, t2q);

    // merged GEMM2 (amp) + GEMM3 (phase, tanh), fp16 outputs
    gemm_f16<3><<<dim3(8, 64, 2), 256, SMEMB>>>(t2q, w3, ab3, nullptr, amph,
                                                pq, pw2, pb2, phh,
                                                1024, 2048);

    qs_kernel<<<(M * 1024) / 1024, 256>>>(amph, phh, rtab, rz, qs);

    // out = qs @ Wfused^T + bfused
    gemm_f16<0><<<dim3(8, 64), 256, SMEMB>>>(qs, wf, bfused, out, nullptr,
                                             nullptr, nullptr, nullptr, nullptr,
                                             1024, 1024);
}